// round 4
// baseline (speedup 1.0000x reference)
#include <cuda_runtime.h>
#include <math_constants.h>

#define N0 16384
#define N1 8192
#define N2 4096
#define N3 2048
#define R2C 4.0f
#define FPS_T 512

// ---------------- device scratch (no allocations allowed) ----------------
__device__ float4 g_p4_0[N0];
__device__ float4 g_p4_1[N1];
__device__ float4 g_p4_2[N2];
__device__ float4 g_p4_3[N3];
__device__ int    g_sel0[N1];
__device__ int    g_sel1[N2];
__device__ int    g_sel2[N3];
__device__ int    g_sori[N0];     // per-level sorted->original index scratch
__device__ float4 g_h0[N0 * 4];   // 16 floats per point
__device__ float4 g_x1[N1 * 4];
__device__ float4 g_x2[N2 * 4];
__device__ float4 g_x3[N3 * 4];
__device__ float4 g_f2[N2 * 4];
__device__ float4 g_f1[N1 * 4];
__device__ float4 g_f0[N0 * 4];

// ---------------- prep: pack pos + squared norm into float4 ----------------
__global__ void prep_kernel(const float* __restrict__ pos) {
    int i = blockIdx.x * blockDim.x + threadIdx.x;
    if (i >= N0) return;
    float x = pos[3 * i], y = pos[3 * i + 1], z = pos[3 * i + 2];
    float nb = __fadd_rn(__fadd_rn(__fmul_rn(x, x), __fmul_rn(y, y)), __fmul_rn(z, z));
    g_p4_0[i] = make_float4(x, y, z, nb);
}

__device__ __forceinline__ void load16(const float4* __restrict__ row, float* v) {
    float4 a = row[0], b = row[1], c = row[2], d = row[3];
    v[0] = a.x; v[1] = a.y; v[2] = a.z; v[3] = a.w;
    v[4] = b.x; v[5] = b.y; v[6] = b.z; v[7] = b.w;
    v[8] = c.x; v[9] = c.y; v[10] = c.z; v[11] = c.w;
    v[12] = d.x; v[13] = d.y; v[14] = d.z; v[15] = d.w;
}

__device__ __forceinline__ void store16(float4* __restrict__ row, const float* v) {
    row[0] = make_float4(v[0], v[1], v[2], v[3]);
    row[1] = make_float4(v[4], v[5], v[6], v[7]);
    row[2] = make_float4(v[8], v[9], v[10], v[11]);
    row[3] = make_float4(v[12], v[13], v[14], v[15]);
}

// ---------------- lin_in ----------------
__global__ void lin_in_kernel(const float* __restrict__ x,
                              const float* __restrict__ W0, const float* __restrict__ b0,
                              const float* __restrict__ W1, const float* __restrict__ b1) {
    __shared__ float sW0[256], sW1[256], sb0[16], sb1[16];
    int t = threadIdx.x;
    for (int i = t; i < 256; i += blockDim.x) { sW0[i] = W0[i]; sW1[i] = W1[i]; }
    if (t < 16) { sb0[t] = b0[t]; sb1[t] = b1[t]; }
    __syncthreads();
    int g = blockIdx.x * blockDim.x + t;
    if (g >= N0) return;
    float in[16], hid[16], out[16];
    load16((const float4*)(x + g * 16), in);
#pragma unroll
    for (int o = 0; o < 16; o++) hid[o] = sb0[o];
#pragma unroll
    for (int i = 0; i < 16; i++) {
        float v = in[i];
#pragma unroll
        for (int o = 0; o < 16; o++) hid[o] = fmaf(v, sW0[i * 16 + o], hid[o]);
    }
#pragma unroll
    for (int o = 0; o < 16; o++) hid[o] = fmaxf(hid[o], 0.0f);
#pragma unroll
    for (int o = 0; o < 16; o++) out[o] = sb1[o];
#pragma unroll
    for (int i = 0; i < 16; i++) {
        float v = hid[i];
#pragma unroll
        for (int o = 0; o < 16; o++) out[o] = fmaf(v, sW1[i * 16 + o], out[o]);
    }
#pragma unroll
    for (int o = 0; o < 16; o++) out[o] = fmaxf(out[o], 0.0f);
    store16(&g_h0[g * 4], out);
}

// ---------------- FPS with spatial sort + AABB pruning, short serial chain ----------------
template <int GB>
__device__ __forceinline__ int mcell(float x, float y, float z) {
    const float inv = (float)(1 << GB) * (1.0f / 32.0f);
    int cx = min((1 << GB) - 1, max(0, (int)(x * inv)));
    int cy = min((1 << GB) - 1, max(0, (int)(y * inv)));
    int cz = min((1 << GB) - 1, max(0, (int)(z * inv)));
    int m = 0;
#pragma unroll
    for (int b = 0; b < GB; b++)
        m |= (((cx >> b) & 1) << (3 * b)) | (((cy >> b) & 1) << (3 * b + 1)) |
             (((cz >> b) & 1) << (3 * b + 2));
    return m;
}

__device__ __forceinline__ unsigned long long umax64(unsigned long long a, unsigned long long b) {
    return a > b ? a : b;
}

// NPTS points, select M, PTS = NPTS/512 points per thread, GB grid bits per dim
template <int NPTS, int M, int PTS, int GB>
__global__ __launch_bounds__(FPS_T, 1)
void fps_kernel(const float4* __restrict__ p4, int* __restrict__ sel, int* __restrict__ sori) {
    constexpr int NCELL = 1 << (3 * GB);
    constexpr int LOGP = (PTS == 32) ? 5 : (PTS == 16) ? 4 : 3;
    __shared__ int s_hist[4096];
    __shared__ __align__(16) unsigned long long s_buf[32];  // [2 parities][16 warps]
    __shared__ int s_misc[24];

    extern __shared__ float sm[];
    float2* pxy = (float2*)sm;
    float* pz = (float*)(pxy + NPTS);

    const int t = threadIdx.x;
    const int lane = t & 31;
    const int wid = t >> 5;

    // ---- phase 1: histogram ----
    for (int i = t; i < NCELL; i += FPS_T) s_hist[i] = 0;
    __syncthreads();
    for (int i = t; i < NPTS; i += FPS_T) {
        float4 p = p4[i];
        atomicAdd(&s_hist[mcell<GB>(p.x, p.y, p.z)], 1);
    }
    __syncthreads();

    // ---- phase 2: exclusive block scan of s_hist[0..NCELL) ----
    {
        constexpr int PER = (NCELL + FPS_T - 1) / FPS_T;
        int base = t * PER;
        int vals[PER];
        int run = 0;
#pragma unroll
        for (int q = 0; q < PER; q++) {
            int v = (base + q < NCELL) ? s_hist[base + q] : 0;
            vals[q] = v;
            run += v;
        }
        int inc = run;
#pragma unroll
        for (int off = 1; off < 32; off <<= 1) {
            int nb = __shfl_up_sync(0xffffffffu, inc, off);
            if (lane >= off) inc += nb;
        }
        if (lane == 31) s_misc[8 + wid] = inc;
        __syncthreads();
        if (t < 32) {
            int w = (t < 16) ? s_misc[8 + t] : 0;
            int winc = w;
#pragma unroll
            for (int off = 1; off < 16; off <<= 1) {
                int nb = __shfl_up_sync(0xffffffffu, winc, off);
                if (t >= off) winc += nb;
            }
            if (t < 16) s_misc[8 + t] = winc - w;
        }
        __syncthreads();
        int off0 = s_misc[8 + wid] + (inc - run);
#pragma unroll
        for (int q = 0; q < PER; q++) {
            if (base + q < NCELL) s_hist[base + q] = off0;
            off0 += vals[q];
        }
    }
    __syncthreads();

    // ---- phase 3: scatter into transposed smem layout ----
    for (int i = t; i < NPTS; i += FPS_T) {
        float4 p = p4[i];
        int d = atomicAdd(&s_hist[mcell<GB>(p.x, p.y, p.z)], 1);
        int slot = (d & (PTS - 1)) * FPS_T + (d >> LOGP);
        pxy[slot] = make_float2(p.x, p.y);
        pz[slot] = p.z;
        sori[d] = i;
        if (i == 0) s_misc[0] = d;
    }
    __syncthreads();

    // ---- phase 4: per-thread AABB (center/halfwidth form) ----
    float mind[PTS];
    float lox = CUDART_INF_F, loy = CUDART_INF_F, loz = CUDART_INF_F;
    float hix = -CUDART_INF_F, hiy = -CUDART_INF_F, hiz = -CUDART_INF_F;
#pragma unroll
    for (int k = 0; k < PTS; k++) {
        int slot = k * FPS_T + t;
        float2 q = pxy[slot];
        float qz = pz[slot];
        lox = fminf(lox, q.x); hix = fmaxf(hix, q.x);
        loy = fminf(loy, q.y); hiy = fmaxf(hiy, q.y);
        loz = fminf(loz, qz); hiz = fmaxf(hiz, qz);
        mind[k] = CUDART_INF_F;
    }
    const float bcx = (lox + hix) * 0.5f, hwx = (hix - lox) * 0.5f;
    const float bcy = (loy + hiy) * 0.5f, hwy = (hiy - loy) * 0.5f;
    const float bcz = (loz + hiz) * 0.5f, hwz = (hiz - loz) * 0.5f;

    if (t == 0) sel[0] = s_misc[0];   // raw sorted index of original point 0
    float chunk_val = CUDART_INF_F;
    int chunk_si = t * PTS;
    unsigned long long warp_key = ((unsigned long long)0x7f800000u) << 32;
    int j = s_misc[0];

    // ---- phase 5: the FPS scan ----
    for (int step = 1; step < M; ++step) {
        int slotj = (j & (PTS - 1)) * FPS_T + (j >> LOGP);
        float2 cxy = pxy[slotj];
        float cz = pz[slotj];

        float ax = fmaxf(fabsf(cxy.x - bcx) - hwx, 0.0f);
        float ay = fmaxf(fabsf(cxy.y - bcy) - hwy, 0.0f);
        float az = fmaxf(fabsf(cz - bcz) - hwz, 0.0f);
        float lb = fmaf(ax, ax, fmaf(ay, ay, az * az)) * 0.9999f;
        bool touch = lb < chunk_val;
        unsigned wm = __ballot_sync(0xffffffffu, touch);
        if (wm) {
            if (touch) {
                float bestv = -1.0f;
                int bestk = 0;
#pragma unroll
                for (int k = 0; k < PTS; k++) {
                    int slot = k * FPS_T + t;
                    float2 q = pxy[slot];
                    float qz = pz[slot];
                    float dx = __fadd_rn(q.x, -cxy.x);
                    float dy = __fadd_rn(q.y, -cxy.y);
                    float dz = __fadd_rn(qz, -cz);
                    float d2 = __fadd_rn(__fadd_rn(__fmul_rn(dx, dx), __fmul_rn(dy, dy)),
                                         __fmul_rn(dz, dz));
                    float mn = fminf(mind[k], d2);
                    mind[k] = mn;
                    if (mn > bestv) { bestv = mn; bestk = k; }
                }
                chunk_val = bestv;
                chunk_si = t * PTS + bestk;
            }
            // value-only butterfly (FMNMX), then resolve winner lane
            float v = chunk_val;
#pragma unroll
            for (int off = 16; off; off >>= 1)
                v = fmaxf(v, __shfl_xor_sync(0xffffffffu, v, off));
            unsigned cm = __ballot_sync(0xffffffffu, chunk_val == v);
            int src = __ffs(cm) - 1;
            int wsi = __shfl_sync(0xffffffffu, chunk_si, src);
            warp_key = (((unsigned long long)__float_as_uint(v)) << 32) | (unsigned)wsi;
        }
        int par = (step & 1) << 4;
        if (lane == 0) s_buf[par + wid] = warp_key;
        __syncthreads();
        // block reduce: every thread loads all 16 keys, register u64 tree
        const ulonglong2* bb = (const ulonglong2*)(s_buf + par);
        ulonglong2 q0 = bb[0], q1 = bb[1], q2 = bb[2], q3 = bb[3];
        ulonglong2 q4 = bb[4], q5 = bb[5], q6 = bb[6], q7 = bb[7];
        unsigned long long m = umax64(
            umax64(umax64(umax64(q0.x, q0.y), umax64(q1.x, q1.y)),
                   umax64(umax64(q2.x, q2.y), umax64(q3.x, q3.y))),
            umax64(umax64(umax64(q4.x, q4.y), umax64(q5.x, q5.y)),
                   umax64(umax64(q6.x, q6.y), umax64(q7.x, q7.y))));
        j = (int)(m & 0xffffffffull);
        if (t == 0) sel[step] = j;   // raw sorted index; remapped below
    }

    // ---- phase 6: remap raw sorted indices to original indices ----
    __syncthreads();
    for (int i = t; i < M; i += FPS_T) {
        int si_ = sel[i];
        sel[i] = sori[si_];
    }
}

// ---------------- gather sampled positions ----------------
__global__ void gather_kernel(const float4* __restrict__ src, const int* __restrict__ sel,
                              float4* __restrict__ dst, int m) {
    int i = blockIdx.x * blockDim.x + threadIdx.x;
    if (i < m) dst[i] = src[sel[i]];
}

// ---------------- SA: radius group + PointConv + max-agg ----------------
template <int NSRC>
__global__ void sa_conv_kernel(const float4* __restrict__ p4s, const float4* __restrict__ p4t,
                               const float4* __restrict__ hs, float4* __restrict__ xt,
                               const float* __restrict__ W0, const float* __restrict__ b0,
                               const float* __restrict__ W1, const float* __restrict__ b1,
                               int ntgt) {
    __shared__ float sW0[19 * 19], sW1[19 * 16], sb0[19], sb1[16];
    int t = threadIdx.x;
    for (int i = t; i < 361; i += blockDim.x) sW0[i] = W0[i];
    for (int i = t; i < 304; i += blockDim.x) sW1[i] = W1[i];
    if (t < 19) sb0[t] = b0[t];
    if (t < 16) sb1[t] = b1[t];
    __syncthreads();

    int warp = (blockIdx.x * blockDim.x + t) >> 5;
    int lane = t & 31;
    if (warp >= ntgt) return;

    float4 pt = p4t[warp];
    float na = pt.w;
    float myd = 0.0f;
    int myj = 0;
    int cnt = 0;

    for (int base = 0; base < NSRC; base += 32) {
        int j = base + lane;
        float4 ps = p4s[j];
        float dot = fmaf(pt.x, ps.x, fmaf(pt.y, ps.y, pt.z * ps.z));
        float d2 = fmaxf((na + ps.w) - 2.0f * dot, 0.0f);
        bool hit = d2 <= R2C;
        unsigned mm = __ballot_sync(0xffffffffu, hit);
        while (mm) {
            int b = __ffs(mm) - 1;
            mm &= mm - 1;
            float nd = __shfl_sync(0xffffffffu, d2, b);
            int nj = base + b;
            if (cnt < 32) {
                if (lane == cnt) { myd = nd; myj = nj; }
                cnt++;
            } else {
                float mv = (lane < cnt) ? myd : -CUDART_INF_F;
                int ml = lane;
#pragma unroll
                for (int off = 16; off; off >>= 1) {
                    float ov = __shfl_xor_sync(0xffffffffu, mv, off);
                    int ol = __shfl_xor_sync(0xffffffffu, ml, off);
                    if (ov > mv) { mv = ov; ml = ol; }
                }
                if (nd < mv && lane == ml) { myd = nd; myj = nj; }
            }
        }
    }

    bool valid = lane < cnt;
    int jj = valid ? myj : 0;
    float in[19];
    load16(&hs[jj * 4], in);
    float4 sp = p4s[jj];
    in[16] = sp.x - pt.x;
    in[17] = sp.y - pt.y;
    in[18] = sp.z - pt.z;

    float hid[19];
#pragma unroll
    for (int o = 0; o < 19; o++) hid[o] = sb0[o];
#pragma unroll
    for (int i = 0; i < 19; i++) {
        float v = in[i];
#pragma unroll
        for (int o = 0; o < 19; o++) hid[o] = fmaf(v, sW0[i * 19 + o], hid[o]);
    }
#pragma unroll
    for (int o = 0; o < 19; o++) hid[o] = fmaxf(hid[o], 0.0f);

    float out[16];
#pragma unroll
    for (int o = 0; o < 16; o++) out[o] = sb1[o];
#pragma unroll
    for (int i = 0; i < 19; i++) {
        float v = hid[i];
#pragma unroll
        for (int o = 0; o < 16; o++) out[o] = fmaf(v, sW1[i * 16 + o], out[o]);
    }
    float res[16];
#pragma unroll
    for (int c = 0; c < 16; c++) {
        float r = valid ? fmaxf(out[c], 0.0f) : -CUDART_INF_F;
#pragma unroll
        for (int off = 16; off; off >>= 1) r = fmaxf(r, __shfl_xor_sync(0xffffffffu, r, off));
        res[c] = r;
    }
    if (lane == 0) store16(&xt[warp * 4], res);
}

// ---------------- FP: kNN(3) interpolate + MLP(32->32->16) ----------------
template <int NC>
__global__ void fp_kernel(const float4* __restrict__ p4f, const float4* __restrict__ p4c,
                          const float4* __restrict__ xc, const float4* __restrict__ xs,
                          float4* __restrict__ xf,
                          const float* __restrict__ W0, const float* __restrict__ b0,
                          const float* __restrict__ W1, const float* __restrict__ b1,
                          int nf) {
    __shared__ float sW0[32 * 32], sW1[32 * 16], sb0[32], sb1[16];
    int t = threadIdx.x;
    for (int i = t; i < 1024; i += blockDim.x) sW0[i] = W0[i];
    for (int i = t; i < 512; i += blockDim.x) sW1[i] = W1[i];
    if (t < 32) sb0[t] = b0[t];
    if (t < 16) sb1[t] = b1[t];
    __syncthreads();

    int g = blockIdx.x * blockDim.x + t;
    if (g >= nf) return;
    float4 f = p4f[g];
    float na = f.w;
    float d0 = CUDART_INF_F, d1 = CUDART_INF_F, d2 = CUDART_INF_F;
    int i0 = 0, i1 = 0, i2 = 0;
    for (int j = 0; j < NC; j++) {
        float4 c = p4c[j];
        float dot = fmaf(f.x, c.x, fmaf(f.y, c.y, f.z * c.z));
        float dd = fmaxf((na + c.w) - 2.0f * dot, 0.0f);
        if (dd < d0) {
            d2 = d1; i2 = i1; d1 = d0; i1 = i0; d0 = dd; i0 = j;
        } else if (dd < d1) {
            d2 = d1; i2 = i1; d1 = dd; i1 = j;
        } else if (dd < d2) {
            d2 = dd; i2 = j;
        }
    }
    float w0 = 1.0f / fmaxf(d0, 1e-16f);
    float w1 = 1.0f / fmaxf(d1, 1e-16f);
    float w2 = 1.0f / fmaxf(d2, 1e-16f);
    float ws = w0 + w1 + w2;
    w0 /= ws; w1 /= ws; w2 /= ws;

    float a0[16], a1[16], a2[16], in[32];
    load16(&xc[i0 * 4], a0);
    load16(&xc[i1 * 4], a1);
    load16(&xc[i2 * 4], a2);
#pragma unroll
    for (int c = 0; c < 16; c++) in[c] = (a0[c] * w0 + a1[c] * w1) + a2[c] * w2;
    load16(&xs[g * 4], in + 16);

    float hid[32];
#pragma unroll
    for (int o = 0; o < 32; o++) hid[o] = sb0[o];
#pragma unroll
    for (int i = 0; i < 32; i++) {
        float v = in[i];
#pragma unroll
        for (int o = 0; o < 32; o++) hid[o] = fmaf(v, sW0[i * 32 + o], hid[o]);
    }
#pragma unroll
    for (int o = 0; o < 32; o++) hid[o] = fmaxf(hid[o], 0.0f);
    float out[16];
#pragma unroll
    for (int o = 0; o < 16; o++) out[o] = sb1[o];
#pragma unroll
    for (int i = 0; i < 32; i++) {
        float v = hid[i];
#pragma unroll
        for (int o = 0; o < 16; o++) out[o] = fmaf(v, sW1[i * 16 + o], out[o]);
    }
#pragma unroll
    for (int o = 0; o < 16; o++) out[o] = fmaxf(out[o], 0.0f);
    store16(&xf[g * 4], out);
}

// ---------------- lin_out ----------------
__global__ void lin_out_kernel(const float* __restrict__ W0, const float* __restrict__ b0,
                               const float* __restrict__ W1, const float* __restrict__ b1,
                               float* __restrict__ out) {
    __shared__ float sW0[256], sW1[32], sb0[16], sb1[2];
    int t = threadIdx.x;
    for (int i = t; i < 256; i += blockDim.x) sW0[i] = W0[i];
    if (t < 32) sW1[t] = W1[t];
    if (t < 16) sb0[t] = b0[t];
    if (t < 2) sb1[t] = b1[t];
    __syncthreads();
    int g = blockIdx.x * blockDim.x + t;
    if (g >= N0) return;
    float in[16], hid[16];
    load16(&g_f0[g * 4], in);
#pragma unroll
    for (int o = 0; o < 16; o++) hid[o] = sb0[o];
#pragma unroll
    for (int i = 0; i < 16; i++) {
        float v = in[i];
#pragma unroll
        for (int o = 0; o < 16; o++) hid[o] = fmaf(v, sW0[i * 16 + o], hid[o]);
    }
    float o0 = sb1[0], o1 = sb1[1];
#pragma unroll
    for (int i = 0; i < 16; i++) {
        float v = fmaxf(hid[i], 0.0f);
        o0 = fmaf(v, sW1[i * 2 + 0], o0);
        o1 = fmaf(v, sW1[i * 2 + 1], o1);
    }
    out[g * 2 + 0] = o0;
    out[g * 2 + 1] = o1;
}

// ---------------- host launcher ----------------
extern "C" void kernel_launch(void* const* d_in, const int* in_sizes, int n_in,
                              void* d_out, int out_size) {
    const float* x = (const float*)d_in[0];
    const float* pos = (const float*)d_in[1];
    const float* liW0 = (const float*)d_in[3];
    const float* lib0 = (const float*)d_in[4];
    const float* liW1 = (const float*)d_in[5];
    const float* lib1 = (const float*)d_in[6];
    const float* saW0 = (const float*)d_in[7];
    const float* sab0 = (const float*)d_in[8];
    const float* saW1 = (const float*)d_in[9];
    const float* sab1 = (const float*)d_in[10];
    const float* fpW0 = (const float*)d_in[11];
    const float* fpb0 = (const float*)d_in[12];
    const float* fpW1 = (const float*)d_in[13];
    const float* fpb1 = (const float*)d_in[14];
    const float* loW0 = (const float*)d_in[15];
    const float* lob0 = (const float*)d_in[16];
    const float* loW1 = (const float*)d_in[17];
    const float* lob1 = (const float*)d_in[18];
    float* out = (float*)d_out;

    void *p40, *p41, *p42, *p43, *s0, *s1, *s2, *sori, *h0, *x1, *x2, *x3, *f2, *f1, *f0;
    cudaGetSymbolAddress(&p40, g_p4_0);
    cudaGetSymbolAddress(&p41, g_p4_1);
    cudaGetSymbolAddress(&p42, g_p4_2);
    cudaGetSymbolAddress(&p43, g_p4_3);
    cudaGetSymbolAddress(&s0, g_sel0);
    cudaGetSymbolAddress(&s1, g_sel1);
    cudaGetSymbolAddress(&s2, g_sel2);
    cudaGetSymbolAddress(&sori, g_sori);
    cudaGetSymbolAddress(&h0, g_h0);
    cudaGetSymbolAddress(&x1, g_x1);
    cudaGetSymbolAddress(&x2, g_x2);
    cudaGetSymbolAddress(&x3, g_x3);
    cudaGetSymbolAddress(&f2, g_f2);
    cudaGetSymbolAddress(&f1, g_f1);
    cudaGetSymbolAddress(&f0, g_f0);

    size_t sm0 = (size_t)N0 * 12;
    size_t sm1 = (size_t)N1 * 12;
    size_t sm2 = (size_t)N2 * 12;
    cudaFuncSetAttribute((const void*)fps_kernel<N0, N1, 32, 4>,
                         cudaFuncAttributeMaxDynamicSharedMemorySize, (int)sm0);
    cudaFuncSetAttribute((const void*)fps_kernel<N1, N2, 16, 3>,
                         cudaFuncAttributeMaxDynamicSharedMemorySize, (int)sm1);
    cudaFuncSetAttribute((const void*)fps_kernel<N2, N3, 8, 3>,
                         cudaFuncAttributeMaxDynamicSharedMemorySize, (int)sm2);

    prep_kernel<<<(N0 + 255) / 256, 256>>>(pos);
    lin_in_kernel<<<N0 / 128, 128>>>(x, liW0, lib0, liW1, lib1);

    // level 0
    fps_kernel<N0, N1, 32, 4><<<1, FPS_T, sm0>>>((const float4*)p40, (int*)s0, (int*)sori);
    gather_kernel<<<N1 / 256, 256>>>((const float4*)p40, (const int*)s0, (float4*)p41, N1);
    sa_conv_kernel<N0><<<N1 * 32 / 256, 256>>>((const float4*)p40, (const float4*)p41,
                                               (const float4*)h0, (float4*)x1,
                                               saW0, sab0, saW1, sab1, N1);
    // level 1
    fps_kernel<N1, N2, 16, 3><<<1, FPS_T, sm1>>>((const float4*)p41, (int*)s1, (int*)sori);
    gather_kernel<<<N2 / 256, 256>>>((const float4*)p41, (const int*)s1, (float4*)p42, N2);
    sa_conv_kernel<N1><<<N2 * 32 / 256, 256>>>((const float4*)p41, (const float4*)p42,
                                               (const float4*)x1, (float4*)x2,
                                               saW0 + 361, sab0 + 19, saW1 + 304, sab1 + 16, N2);
    // level 2
    fps_kernel<N2, N3, 8, 3><<<1, FPS_T, sm2>>>((const float4*)p42, (int*)s2, (int*)sori);
    gather_kernel<<<N3 / 256, 256>>>((const float4*)p42, (const int*)s2, (float4*)p43, N3);
    sa_conv_kernel<N2><<<N3 * 32 / 256, 256>>>((const float4*)p42, (const float4*)p43,
                                               (const float4*)x2, (float4*)x3,
                                               saW0 + 722, sab0 + 38, saW1 + 608, sab1 + 32, N3);

    // FP path (coarse -> fine)
    fp_kernel<N3><<<N2 / 128, 128>>>((const float4*)p42, (const float4*)p43,
                                     (const float4*)x3, (const float4*)x2, (float4*)f2,
                                     fpW0 + 2 * 1024, fpb0 + 2 * 32, fpW1 + 2 * 512, fpb1 + 2 * 16,
                                     N2);
    fp_kernel<N2><<<N1 / 128, 128>>>((const float4*)p41, (const float4*)p42,
                                     (const float4*)f2, (const float4*)x1, (float4*)f1,
                                     fpW0 + 1024, fpb0 + 32, fpW1 + 512, fpb1 + 16, N1);
    fp_kernel<N1><<<N0 / 128, 128>>>((const float4*)p40, (const float4*)p41,
                                     (const float4*)f1, (const float4*)h0, (float4*)f0,
                                     fpW0, fpb0, fpW1, fpb1, N0);

    lin_out_kernel<<<N0 / 256, 256>>>(loW0, lob0, loW1, lob1, out);
}

// round 5
// speedup vs baseline: 1.5451x; 1.5451x over previous
#include <cuda_runtime.h>
#include <math_constants.h>

#define N0 16384
#define N1 8192
#define N2 4096
#define N3 2048
#define R2C 4.0f
#define FPS_T 512

// ---------------- device scratch (no allocations allowed) ----------------
__device__ float4 g_p4_0[N0];
__device__ float4 g_p4_1[N1];
__device__ float4 g_p4_2[N2];
__device__ float4 g_p4_3[N3];
__device__ int    g_sel0[N1];
__device__ int    g_sel1[N2];
__device__ int    g_sel2[N3];
__device__ int    g_sori[N0];     // per-level sorted->original index scratch
__device__ float4 g_h0[N0 * 4];   // 16 floats per point
__device__ float4 g_x1[N1 * 4];
__device__ float4 g_x2[N2 * 4];
__device__ float4 g_x3[N3 * 4];
__device__ float4 g_f2[N2 * 4];
__device__ float4 g_f1[N1 * 4];
__device__ float4 g_f0[N0 * 4];

// ---------------- prep: pack pos + squared norm into float4 ----------------
__global__ void prep_kernel(const float* __restrict__ pos) {
    int i = blockIdx.x * blockDim.x + threadIdx.x;
    if (i >= N0) return;
    float x = pos[3 * i], y = pos[3 * i + 1], z = pos[3 * i + 2];
    float nb = __fadd_rn(__fadd_rn(__fmul_rn(x, x), __fmul_rn(y, y)), __fmul_rn(z, z));
    g_p4_0[i] = make_float4(x, y, z, nb);
}

__device__ __forceinline__ void load16(const float4* __restrict__ row, float* v) {
    float4 a = row[0], b = row[1], c = row[2], d = row[3];
    v[0] = a.x; v[1] = a.y; v[2] = a.z; v[3] = a.w;
    v[4] = b.x; v[5] = b.y; v[6] = b.z; v[7] = b.w;
    v[8] = c.x; v[9] = c.y; v[10] = c.z; v[11] = c.w;
    v[12] = d.x; v[13] = d.y; v[14] = d.z; v[15] = d.w;
}

__device__ __forceinline__ void store16(float4* __restrict__ row, const float* v) {
    row[0] = make_float4(v[0], v[1], v[2], v[3]);
    row[1] = make_float4(v[4], v[5], v[6], v[7]);
    row[2] = make_float4(v[8], v[9], v[10], v[11]);
    row[3] = make_float4(v[12], v[13], v[14], v[15]);
}

// ---------------- lin_in ----------------
__global__ void lin_in_kernel(const float* __restrict__ x,
                              const float* __restrict__ W0, const float* __restrict__ b0,
                              const float* __restrict__ W1, const float* __restrict__ b1) {
    __shared__ float sW0[256], sW1[256], sb0[16], sb1[16];
    int t = threadIdx.x;
    for (int i = t; i < 256; i += blockDim.x) { sW0[i] = W0[i]; sW1[i] = W1[i]; }
    if (t < 16) { sb0[t] = b0[t]; sb1[t] = b1[t]; }
    __syncthreads();
    int g = blockIdx.x * blockDim.x + t;
    if (g >= N0) return;
    float in[16], hid[16], out[16];
    load16((const float4*)(x + g * 16), in);
#pragma unroll
    for (int o = 0; o < 16; o++) hid[o] = sb0[o];
#pragma unroll
    for (int i = 0; i < 16; i++) {
        float v = in[i];
#pragma unroll
        for (int o = 0; o < 16; o++) hid[o] = fmaf(v, sW0[i * 16 + o], hid[o]);
    }
#pragma unroll
    for (int o = 0; o < 16; o++) hid[o] = fmaxf(hid[o], 0.0f);
#pragma unroll
    for (int o = 0; o < 16; o++) out[o] = sb1[o];
#pragma unroll
    for (int i = 0; i < 16; i++) {
        float v = hid[i];
#pragma unroll
        for (int o = 0; o < 16; o++) out[o] = fmaf(v, sW1[i * 16 + o], out[o]);
    }
#pragma unroll
    for (int o = 0; o < 16; o++) out[o] = fmaxf(out[o], 0.0f);
    store16(&g_h0[g * 4], out);
}

// ---------------- FPS with spatial sort + AABB pruning + atomic reduce ----------------
template <int GB>
__device__ __forceinline__ int mcell(float x, float y, float z) {
    const float inv = (float)(1 << GB) * (1.0f / 32.0f);
    int cx = min((1 << GB) - 1, max(0, (int)(x * inv)));
    int cy = min((1 << GB) - 1, max(0, (int)(y * inv)));
    int cz = min((1 << GB) - 1, max(0, (int)(z * inv)));
    int m = 0;
#pragma unroll
    for (int b = 0; b < GB; b++)
        m |= (((cx >> b) & 1) << (3 * b)) | (((cy >> b) & 1) << (3 * b + 1)) |
             (((cz >> b) & 1) << (3 * b + 2));
    return m;
}

// NPTS points, select M, PTS = NPTS/512 points per thread, GB grid bits per dim
template <int NPTS, int M, int PTS, int GB>
__global__ __launch_bounds__(FPS_T, 1)
void fps_kernel(const float4* __restrict__ p4, int* __restrict__ sel, int* __restrict__ sori) {
    constexpr int NCELL = 1 << (3 * GB);
    constexpr int LOGP = (PTS == 32) ? 5 : (PTS == 16) ? 4 : 3;
    __shared__ int s_hist[4096];
    __shared__ __align__(64) unsigned s_vmax[2][16];
    __shared__ unsigned s_imin[2];
    __shared__ int s_misc[24];

    extern __shared__ float sm[];
    float* px = sm;
    float* py = sm + NPTS;
    float* pz = sm + 2 * NPTS;

    const int t = threadIdx.x;
    const int lane = t & 31;
    const int wid = t >> 5;

    // ---- phase 1: histogram ----
    for (int i = t; i < NCELL; i += FPS_T) s_hist[i] = 0;
    if (t < 16) { s_vmax[0][t] = 0u; s_vmax[1][t] = 0u; }
    if (t == 0) { s_imin[0] = 0xffffffffu; s_imin[1] = 0xffffffffu; }
    __syncthreads();
    for (int i = t; i < NPTS; i += FPS_T) {
        float4 p = p4[i];
        atomicAdd(&s_hist[mcell<GB>(p.x, p.y, p.z)], 1);
    }
    __syncthreads();

    // ---- phase 2: exclusive block scan of s_hist[0..NCELL) ----
    {
        constexpr int PER = (NCELL + FPS_T - 1) / FPS_T;
        int base = t * PER;
        int vals[PER];
        int run = 0;
#pragma unroll
        for (int q = 0; q < PER; q++) {
            int v = (base + q < NCELL) ? s_hist[base + q] : 0;
            vals[q] = v;
            run += v;
        }
        int inc = run;
#pragma unroll
        for (int off = 1; off < 32; off <<= 1) {
            int nb = __shfl_up_sync(0xffffffffu, inc, off);
            if (lane >= off) inc += nb;
        }
        if (lane == 31) s_misc[8 + wid] = inc;
        __syncthreads();
        if (t < 32) {
            int w = (t < 16) ? s_misc[8 + t] : 0;
            int winc = w;
#pragma unroll
            for (int off = 1; off < 16; off <<= 1) {
                int nb = __shfl_up_sync(0xffffffffu, winc, off);
                if (t >= off) winc += nb;
            }
            if (t < 16) s_misc[8 + t] = winc - w;
        }
        __syncthreads();
        int off0 = s_misc[8 + wid] + (inc - run);
#pragma unroll
        for (int q = 0; q < PER; q++) {
            if (base + q < NCELL) s_hist[base + q] = off0;
            off0 += vals[q];
        }
    }
    __syncthreads();

    // ---- phase 3: scatter into transposed smem layout ----
    for (int i = t; i < NPTS; i += FPS_T) {
        float4 p = p4[i];
        int d = atomicAdd(&s_hist[mcell<GB>(p.x, p.y, p.z)], 1);
        int slot = (d & (PTS - 1)) * FPS_T + (d >> LOGP);
        px[slot] = p.x; py[slot] = p.y; pz[slot] = p.z;
        sori[d] = i;
        if (i == 0) s_misc[0] = d;
    }
    __syncthreads();

    // ---- phase 4: per-thread AABB + mind init ----
    float mind[PTS];
    float lox = CUDART_INF_F, loy = CUDART_INF_F, loz = CUDART_INF_F;
    float hix = -CUDART_INF_F, hiy = -CUDART_INF_F, hiz = -CUDART_INF_F;
#pragma unroll
    for (int k = 0; k < PTS; k++) {
        int slot = k * FPS_T + t;
        float X = px[slot], Y = py[slot], Z = pz[slot];
        lox = fminf(lox, X); hix = fmaxf(hix, X);
        loy = fminf(loy, Y); hiy = fmaxf(hiy, Y);
        loz = fminf(loz, Z); hiz = fmaxf(hiz, Z);
        mind[k] = CUDART_INF_F;
    }

    float chunk_val = CUDART_INF_F;
    int chunk_si = t * PTS;
    int j = s_misc[0];
    if (t == 0) sel[0] = j;

    // ---- phase 5: the FPS scan (atomic two-stage argmax) ----
    for (int step = 1; step < M; ++step) {
        int slotj = (j & (PTS - 1)) * FPS_T + (j >> LOGP);
        float cx = px[slotj], cy = py[slotj], cz = pz[slotj];

        float ax = fmaxf(fmaxf(lox - cx, cx - hix), 0.0f);
        float ay = fmaxf(fmaxf(loy - cy, cy - hiy), 0.0f);
        float az = fmaxf(fmaxf(loz - cz, cz - hiz), 0.0f);
        float lb = fmaf(ax, ax, fmaf(ay, ay, az * az)) * 0.9999f;

        if (lb < chunk_val) {
#pragma unroll
            for (int k = 0; k < PTS; k++) {
                int slot = k * FPS_T + t;
                float dx = __fadd_rn(px[slot], -cx);
                float dy = __fadd_rn(py[slot], -cy);
                float dz = __fadd_rn(pz[slot], -cz);
                float d2 = __fadd_rn(__fadd_rn(__fmul_rn(dx, dx), __fmul_rn(dy, dy)),
                                     __fmul_rn(dz, dz));
                mind[k] = fminf(mind[k], d2);
            }
            // value-only tournament max over mind[]
            float red[PTS];
#pragma unroll
            for (int k = 0; k < PTS; k++) red[k] = mind[k];
#pragma unroll
            for (int w = PTS / 2; w >= 1; w >>= 1)
#pragma unroll
                for (int k = 0; k < PTS / 2; k++)
                    if (k < w) red[k] = fmaxf(red[k], red[k + w]);
            float bv = red[0];
            // first index achieving bv (independent compares -> mask)
            unsigned msk = 0u;
#pragma unroll
            for (int k = 0; k < PTS; k++)
                if (mind[k] == bv) msk |= (1u << k);
            chunk_val = bv;
            chunk_si = t * PTS + (__ffs(msk) - 1);
        }

        int par = step & 1;
        atomicMax(&s_vmax[par][wid], __float_as_uint(chunk_val));
        __syncthreads();

        uint4 a0 = *(const uint4*)&s_vmax[par][0];
        uint4 a1 = *(const uint4*)&s_vmax[par][4];
        uint4 a2 = *(const uint4*)&s_vmax[par][8];
        uint4 a3 = *(const uint4*)&s_vmax[par][12];
        unsigned vm = max(max(max(max(a0.x, a0.y), max(a0.z, a0.w)),
                              max(max(a1.x, a1.y), max(a1.z, a1.w))),
                          max(max(max(a2.x, a2.y), max(a2.z, a2.w)),
                              max(max(a3.x, a3.y), max(a3.z, a3.w))));
        if (__float_as_uint(chunk_val) == vm)
            atomicMin(&s_imin[par], (unsigned)chunk_si);
        __syncthreads();

        j = (int)s_imin[par];
        if (t == 0) sel[step] = j;
        // clear other parity for the next step (safe: program order within
        // warp w for s_vmax[.][w]; barrier transitivity for s_imin)
        if (lane == 0) s_vmax[par ^ 1][wid] = 0u;
        if (t == 0) s_imin[par ^ 1] = 0xffffffffu;
    }

    // ---- phase 6: remap raw sorted indices to original indices ----
    __syncthreads();
    for (int i = t; i < M; i += FPS_T) {
        int si_ = sel[i];
        sel[i] = sori[si_];
    }
}

// ---------------- gather sampled positions ----------------
__global__ void gather_kernel(const float4* __restrict__ src, const int* __restrict__ sel,
                              float4* __restrict__ dst, int m) {
    int i = blockIdx.x * blockDim.x + threadIdx.x;
    if (i < m) dst[i] = src[sel[i]];
}

// ---------------- SA: radius group + PointConv + max-agg ----------------
template <int NSRC>
__global__ void sa_conv_kernel(const float4* __restrict__ p4s, const float4* __restrict__ p4t,
                               const float4* __restrict__ hs, float4* __restrict__ xt,
                               const float* __restrict__ W0, const float* __restrict__ b0,
                               const float* __restrict__ W1, const float* __restrict__ b1,
                               int ntgt) {
    __shared__ float sW0[19 * 19], sW1[19 * 16], sb0[19], sb1[16];
    int t = threadIdx.x;
    for (int i = t; i < 361; i += blockDim.x) sW0[i] = W0[i];
    for (int i = t; i < 304; i += blockDim.x) sW1[i] = W1[i];
    if (t < 19) sb0[t] = b0[t];
    if (t < 16) sb1[t] = b1[t];
    __syncthreads();

    int warp = (blockIdx.x * blockDim.x + t) >> 5;
    int lane = t & 31;
    if (warp >= ntgt) return;

    float4 pt = p4t[warp];
    float na = pt.w;
    float myd = 0.0f;
    int myj = 0;
    int cnt = 0;

    for (int base = 0; base < NSRC; base += 32) {
        int j = base + lane;
        float4 ps = p4s[j];
        float dot = fmaf(pt.x, ps.x, fmaf(pt.y, ps.y, pt.z * ps.z));
        float d2 = fmaxf((na + ps.w) - 2.0f * dot, 0.0f);
        bool hit = d2 <= R2C;
        unsigned mm = __ballot_sync(0xffffffffu, hit);
        while (mm) {
            int b = __ffs(mm) - 1;
            mm &= mm - 1;
            float nd = __shfl_sync(0xffffffffu, d2, b);
            int nj = base + b;
            if (cnt < 32) {
                if (lane == cnt) { myd = nd; myj = nj; }
                cnt++;
            } else {
                float mv = (lane < cnt) ? myd : -CUDART_INF_F;
                int ml = lane;
#pragma unroll
                for (int off = 16; off; off >>= 1) {
                    float ov = __shfl_xor_sync(0xffffffffu, mv, off);
                    int ol = __shfl_xor_sync(0xffffffffu, ml, off);
                    if (ov > mv) { mv = ov; ml = ol; }
                }
                if (nd < mv && lane == ml) { myd = nd; myj = nj; }
            }
        }
    }

    bool valid = lane < cnt;
    int jj = valid ? myj : 0;
    float in[19];
    load16(&hs[jj * 4], in);
    float4 sp = p4s[jj];
    in[16] = sp.x - pt.x;
    in[17] = sp.y - pt.y;
    in[18] = sp.z - pt.z;

    float hid[19];
#pragma unroll
    for (int o = 0; o < 19; o++) hid[o] = sb0[o];
#pragma unroll
    for (int i = 0; i < 19; i++) {
        float v = in[i];
#pragma unroll
        for (int o = 0; o < 19; o++) hid[o] = fmaf(v, sW0[i * 19 + o], hid[o]);
    }
#pragma unroll
    for (int o = 0; o < 19; o++) hid[o] = fmaxf(hid[o], 0.0f);

    float out[16];
#pragma unroll
    for (int o = 0; o < 16; o++) out[o] = sb1[o];
#pragma unroll
    for (int i = 0; i < 19; i++) {
        float v = hid[i];
#pragma unroll
        for (int o = 0; o < 16; o++) out[o] = fmaf(v, sW1[i * 16 + o], out[o]);
    }
    float res[16];
#pragma unroll
    for (int c = 0; c < 16; c++) {
        float r = valid ? fmaxf(out[c], 0.0f) : -CUDART_INF_F;
#pragma unroll
        for (int off = 16; off; off >>= 1) r = fmaxf(r, __shfl_xor_sync(0xffffffffu, r, off));
        res[c] = r;
    }
    if (lane == 0) store16(&xt[warp * 4], res);
}

// ---------------- FP: kNN(3) interpolate + MLP(32->32->16) ----------------
template <int NC>
__global__ void fp_kernel(const float4* __restrict__ p4f, const float4* __restrict__ p4c,
                          const float4* __restrict__ xc, const float4* __restrict__ xs,
                          float4* __restrict__ xf,
                          const float* __restrict__ W0, const float* __restrict__ b0,
                          const float* __restrict__ W1, const float* __restrict__ b1,
                          int nf) {
    __shared__ float sW0[32 * 32], sW1[32 * 16], sb0[32], sb1[16];
    int t = threadIdx.x;
    for (int i = t; i < 1024; i += blockDim.x) sW0[i] = W0[i];
    for (int i = t; i < 512; i += blockDim.x) sW1[i] = W1[i];
    if (t < 32) sb0[t] = b0[t];
    if (t < 16) sb1[t] = b1[t];
    __syncthreads();

    int g = blockIdx.x * blockDim.x + t;
    if (g >= nf) return;
    float4 f = p4f[g];
    float na = f.w;
    float d0 = CUDART_INF_F, d1 = CUDART_INF_F, d2 = CUDART_INF_F;
    int i0 = 0, i1 = 0, i2 = 0;
    for (int j = 0; j < NC; j++) {
        float4 c = p4c[j];
        float dot = fmaf(f.x, c.x, fmaf(f.y, c.y, f.z * c.z));
        float dd = fmaxf((na + c.w) - 2.0f * dot, 0.0f);
        if (dd < d0) {
            d2 = d1; i2 = i1; d1 = d0; i1 = i0; d0 = dd; i0 = j;
        } else if (dd < d1) {
            d2 = d1; i2 = i1; d1 = dd; i1 = j;
        } else if (dd < d2) {
            d2 = dd; i2 = j;
        }
    }
    float w0 = 1.0f / fmaxf(d0, 1e-16f);
    float w1 = 1.0f / fmaxf(d1, 1e-16f);
    float w2 = 1.0f / fmaxf(d2, 1e-16f);
    float ws = w0 + w1 + w2;
    w0 /= ws; w1 /= ws; w2 /= ws;

    float a0[16], a1[16], a2[16], in[32];
    load16(&xc[i0 * 4], a0);
    load16(&xc[i1 * 4], a1);
    load16(&xc[i2 * 4], a2);
#pragma unroll
    for (int c = 0; c < 16; c++) in[c] = (a0[c] * w0 + a1[c] * w1) + a2[c] * w2;
    load16(&xs[g * 4], in + 16);

    float hid[32];
#pragma unroll
    for (int o = 0; o < 32; o++) hid[o] = sb0[o];
#pragma unroll
    for (int i = 0; i < 32; i++) {
        float v = in[i];
#pragma unroll
        for (int o = 0; o < 32; o++) hid[o] = fmaf(v, sW0[i * 32 + o], hid[o]);
    }
#pragma unroll
    for (int o = 0; o < 32; o++) hid[o] = fmaxf(hid[o], 0.0f);
    float out[16];
#pragma unroll
    for (int o = 0; o < 16; o++) out[o] = sb1[o];
#pragma unroll
    for (int i = 0; i < 32; i++) {
        float v = hid[i];
#pragma unroll
        for (int o = 0; o < 16; o++) out[o] = fmaf(v, sW1[i * 16 + o], out[o]);
    }
#pragma unroll
    for (int o = 0; o < 16; o++) out[o] = fmaxf(out[o], 0.0f);
    store16(&xf[g * 4], out);
}

// ---------------- lin_out ----------------
__global__ void lin_out_kernel(const float* __restrict__ W0, const float* __restrict__ b0,
                               const float* __restrict__ W1, const float* __restrict__ b1,
                               float* __restrict__ out) {
    __shared__ float sW0[256], sW1[32], sb0[16], sb1[2];
    int t = threadIdx.x;
    for (int i = t; i < 256; i += blockDim.x) sW0[i] = W0[i];
    if (t < 32) sW1[t] = W1[t];
    if (t < 16) sb0[t] = b0[t];
    if (t < 2) sb1[t] = b1[t];
    __syncthreads();
    int g = blockIdx.x * blockDim.x + t;
    if (g >= N0) return;
    float in[16], hid[16];
    load16(&g_f0[g * 4], in);
#pragma unroll
    for (int o = 0; o < 16; o++) hid[o] = sb0[o];
#pragma unroll
    for (int i = 0; i < 16; i++) {
        float v = in[i];
#pragma unroll
        for (int o = 0; o < 16; o++) hid[o] = fmaf(v, sW0[i * 16 + o], hid[o]);
    }
    float o0 = sb1[0], o1 = sb1[1];
#pragma unroll
    for (int i = 0; i < 16; i++) {
        float v = fmaxf(hid[i], 0.0f);
        o0 = fmaf(v, sW1[i * 2 + 0], o0);
        o1 = fmaf(v, sW1[i * 2 + 1], o1);
    }
    out[g * 2 + 0] = o0;
    out[g * 2 + 1] = o1;
}

// ---------------- host launcher ----------------
extern "C" void kernel_launch(void* const* d_in, const int* in_sizes, int n_in,
                              void* d_out, int out_size) {
    const float* x = (const float*)d_in[0];
    const float* pos = (const float*)d_in[1];
    const float* liW0 = (const float*)d_in[3];
    const float* lib0 = (const float*)d_in[4];
    const float* liW1 = (const float*)d_in[5];
    const float* lib1 = (const float*)d_in[6];
    const float* saW0 = (const float*)d_in[7];
    const float* sab0 = (const float*)d_in[8];
    const float* saW1 = (const float*)d_in[9];
    const float* sab1 = (const float*)d_in[10];
    const float* fpW0 = (const float*)d_in[11];
    const float* fpb0 = (const float*)d_in[12];
    const float* fpW1 = (const float*)d_in[13];
    const float* fpb1 = (const float*)d_in[14];
    const float* loW0 = (const float*)d_in[15];
    const float* lob0 = (const float*)d_in[16];
    const float* loW1 = (const float*)d_in[17];
    const float* lob1 = (const float*)d_in[18];
    float* out = (float*)d_out;

    void *p40, *p41, *p42, *p43, *s0, *s1, *s2, *sori, *h0, *x1, *x2, *x3, *f2, *f1, *f0;
    cudaGetSymbolAddress(&p40, g_p4_0);
    cudaGetSymbolAddress(&p41, g_p4_1);
    cudaGetSymbolAddress(&p42, g_p4_2);
    cudaGetSymbolAddress(&p43, g_p4_3);
    cudaGetSymbolAddress(&s0, g_sel0);
    cudaGetSymbolAddress(&s1, g_sel1);
    cudaGetSymbolAddress(&s2, g_sel2);
    cudaGetSymbolAddress(&sori, g_sori);
    cudaGetSymbolAddress(&h0, g_h0);
    cudaGetSymbolAddress(&x1, g_x1);
    cudaGetSymbolAddress(&x2, g_x2);
    cudaGetSymbolAddress(&x3, g_x3);
    cudaGetSymbolAddress(&f2, g_f2);
    cudaGetSymbolAddress(&f1, g_f1);
    cudaGetSymbolAddress(&f0, g_f0);

    size_t sm0 = (size_t)N0 * 12;
    size_t sm1 = (size_t)N1 * 12;
    size_t sm2 = (size_t)N2 * 12;
    cudaFuncSetAttribute((const void*)fps_kernel<N0, N1, 32, 4>,
                         cudaFuncAttributeMaxDynamicSharedMemorySize, (int)sm0);
    cudaFuncSetAttribute((const void*)fps_kernel<N1, N2, 16, 3>,
                         cudaFuncAttributeMaxDynamicSharedMemorySize, (int)sm1);
    cudaFuncSetAttribute((const void*)fps_kernel<N2, N3, 8, 3>,
                         cudaFuncAttributeMaxDynamicSharedMemorySize, (int)sm2);

    prep_kernel<<<(N0 + 255) / 256, 256>>>(pos);
    lin_in_kernel<<<N0 / 128, 128>>>(x, liW0, lib0, liW1, lib1);

    // level 0
    fps_kernel<N0, N1, 32, 4><<<1, FPS_T, sm0>>>((const float4*)p40, (int*)s0, (int*)sori);
    gather_kernel<<<N1 / 256, 256>>>((const float4*)p40, (const int*)s0, (float4*)p41, N1);
    sa_conv_kernel<N0><<<N1 * 32 / 256, 256>>>((const float4*)p40, (const float4*)p41,
                                               (const float4*)h0, (float4*)x1,
                                               saW0, sab0, saW1, sab1, N1);
    // level 1
    fps_kernel<N1, N2, 16, 3><<<1, FPS_T, sm1>>>((const float4*)p41, (int*)s1, (int*)sori);
    gather_kernel<<<N2 / 256, 256>>>((const float4*)p41, (const int*)s1, (float4*)p42, N2);
    sa_conv_kernel<N1><<<N2 * 32 / 256, 256>>>((const float4*)p41, (const float4*)p42,
                                               (const float4*)x1, (float4*)x2,
                                               saW0 + 361, sab0 + 19, saW1 + 304, sab1 + 16, N2);
    // level 2
    fps_kernel<N2, N3, 8, 3><<<1, FPS_T, sm2>>>((const float4*)p42, (int*)s2, (int*)sori);
    gather_kernel<<<N3 / 256, 256>>>((const float4*)p42, (const int*)s2, (float4*)p43, N3);
    sa_conv_kernel<N2><<<N3 * 32 / 256, 256>>>((const float4*)p42, (const float4*)p43,
                                               (const float4*)x2, (float4*)x3,
                                               saW0 + 722, sab0 + 38, saW1 + 608, sab1 + 32, N3);

    // FP path (coarse -> fine)
    fp_kernel<N3><<<N2 / 128, 128>>>((const float4*)p42, (const float4*)p43,
                                     (const float4*)x3, (const float4*)x2, (float4*)f2,
                                     fpW0 + 2 * 1024, fpb0 + 2 * 32, fpW1 + 2 * 512, fpb1 + 2 * 16,
                                     N2);
    fp_kernel<N2><<<N1 / 128, 128>>>((const float4*)p41, (const float4*)p42,
                                     (const float4*)f2, (const float4*)x1, (float4*)f1,
                                     fpW0 + 1024, fpb0 + 32, fpW1 + 512, fpb1 + 16, N1);
    fp_kernel<N1><<<N0 / 128, 128>>>((const float4*)p40, (const float4*)p41,
                                     (const float4*)f1, (const float4*)h0, (float4*)f0,
                                     fpW0, fpb0, fpW1, fpb1, N0);

    lin_out_kernel<<<N0 / 256, 256>>>(loW0, lob0, loW1, lob1, out);
}

// round 7
// speedup vs baseline: 1.9354x; 1.2526x over previous
#include <cuda_runtime.h>
#include <math_constants.h>

#define N0 16384
#define N1 8192
#define N2 4096
#define N3 2048
#define R2C 4.0f
#define FPS_T 512

// ---------------- device scratch (no allocations allowed) ----------------
__device__ float4 g_p4_0[N0];
__device__ float4 g_p4_1[N1];
__device__ float4 g_p4_2[N2];
__device__ float4 g_p4_3[N3];
__device__ int    g_sel0[N1];
__device__ int    g_sel1[N2];
__device__ int    g_sel2[N3];
__device__ int    g_sori[N0];     // per-level sorted->original index scratch
__device__ float4 g_h0[N0 * 4];   // 16 floats per point
__device__ float4 g_x1[N1 * 4];
__device__ float4 g_x2[N2 * 4];
__device__ float4 g_x3[N3 * 4];
__device__ float4 g_f2[N2 * 4];
__device__ float4 g_f1[N1 * 4];
__device__ float4 g_f0[N0 * 4];

// ---------------- prep: pack pos + squared norm into float4 ----------------
__global__ void prep_kernel(const float* __restrict__ pos) {
    int i = blockIdx.x * blockDim.x + threadIdx.x;
    if (i >= N0) return;
    float x = pos[3 * i], y = pos[3 * i + 1], z = pos[3 * i + 2];
    float nb = __fadd_rn(__fadd_rn(__fmul_rn(x, x), __fmul_rn(y, y)), __fmul_rn(z, z));
    g_p4_0[i] = make_float4(x, y, z, nb);
}

__device__ __forceinline__ void load16(const float4* __restrict__ row, float* v) {
    float4 a = row[0], b = row[1], c = row[2], d = row[3];
    v[0] = a.x; v[1] = a.y; v[2] = a.z; v[3] = a.w;
    v[4] = b.x; v[5] = b.y; v[6] = b.z; v[7] = b.w;
    v[8] = c.x; v[9] = c.y; v[10] = c.z; v[11] = c.w;
    v[12] = d.x; v[13] = d.y; v[14] = d.z; v[15] = d.w;
}

__device__ __forceinline__ void store16(float4* __restrict__ row, const float* v) {
    row[0] = make_float4(v[0], v[1], v[2], v[3]);
    row[1] = make_float4(v[4], v[5], v[6], v[7]);
    row[2] = make_float4(v[8], v[9], v[10], v[11]);
    row[3] = make_float4(v[12], v[13], v[14], v[15]);
}

// ---------------- lin_in ----------------
__global__ void lin_in_kernel(const float* __restrict__ x,
                              const float* __restrict__ W0, const float* __restrict__ b0,
                              const float* __restrict__ W1, const float* __restrict__ b1) {
    __shared__ float sW0[256], sW1[256], sb0[16], sb1[16];
    int t = threadIdx.x;
    for (int i = t; i < 256; i += blockDim.x) { sW0[i] = W0[i]; sW1[i] = W1[i]; }
    if (t < 16) { sb0[t] = b0[t]; sb1[t] = b1[t]; }
    __syncthreads();
    int g = blockIdx.x * blockDim.x + t;
    if (g >= N0) return;
    float in[16], hid[16], out[16];
    load16((const float4*)(x + g * 16), in);
#pragma unroll
    for (int o = 0; o < 16; o++) hid[o] = sb0[o];
#pragma unroll
    for (int i = 0; i < 16; i++) {
        float v = in[i];
#pragma unroll
        for (int o = 0; o < 16; o++) hid[o] = fmaf(v, sW0[i * 16 + o], hid[o]);
    }
#pragma unroll
    for (int o = 0; o < 16; o++) hid[o] = fmaxf(hid[o], 0.0f);
#pragma unroll
    for (int o = 0; o < 16; o++) out[o] = sb1[o];
#pragma unroll
    for (int i = 0; i < 16; i++) {
        float v = hid[i];
#pragma unroll
        for (int o = 0; o < 16; o++) out[o] = fmaf(v, sW1[i * 16 + o], out[o]);
    }
#pragma unroll
    for (int o = 0; o < 16; o++) out[o] = fmaxf(out[o], 0.0f);
    store16(&g_h0[g * 4], out);
}

// ---------------- FPS with spatial sort + AABB pruning + REDUX argmax ----------------
template <int GB>
__device__ __forceinline__ int mcell(float x, float y, float z) {
    const float inv = (float)(1 << GB) * (1.0f / 32.0f);
    int cx = min((1 << GB) - 1, max(0, (int)(x * inv)));
    int cy = min((1 << GB) - 1, max(0, (int)(y * inv)));
    int cz = min((1 << GB) - 1, max(0, (int)(z * inv)));
    int m = 0;
#pragma unroll
    for (int b = 0; b < GB; b++)
        m |= (((cx >> b) & 1) << (3 * b)) | (((cy >> b) & 1) << (3 * b + 1)) |
             (((cz >> b) & 1) << (3 * b + 2));
    return m;
}

// NPTS points, select M, PTS = NPTS/512 points per thread, GB grid bits per dim
template <int NPTS, int M, int PTS, int GB>
__global__ __launch_bounds__(FPS_T, 1)
void fps_kernel(const float4* __restrict__ p4, int* __restrict__ sel, int* __restrict__ sori) {
    constexpr int NCELL = 1 << (3 * GB);
    constexpr int LOGP = (PTS == 32) ? 5 : (PTS == 16) ? 4 : 3;
    __shared__ int s_hist[4096];
    __shared__ unsigned s_val[32];   // [2 parities][16 warps]
    __shared__ int s_si[32];
    __shared__ int s_misc[24];

    extern __shared__ float sm[];
    float* px = sm;
    float* py = sm + NPTS;
    float* pz = sm + 2 * NPTS;

    const int t = threadIdx.x;
    const int lane = t & 31;
    const int wid = t >> 5;

    // ---- phase 1: histogram ----
    for (int i = t; i < NCELL; i += FPS_T) s_hist[i] = 0;
    __syncthreads();
    for (int i = t; i < NPTS; i += FPS_T) {
        float4 p = p4[i];
        atomicAdd(&s_hist[mcell<GB>(p.x, p.y, p.z)], 1);
    }
    __syncthreads();

    // ---- phase 2: exclusive block scan of s_hist[0..NCELL) ----
    {
        constexpr int PER = (NCELL + FPS_T - 1) / FPS_T;
        int base = t * PER;
        int vals[PER];
        int run = 0;
#pragma unroll
        for (int q = 0; q < PER; q++) {
            int v = (base + q < NCELL) ? s_hist[base + q] : 0;
            vals[q] = v;
            run += v;
        }
        int inc = run;
#pragma unroll
        for (int off = 1; off < 32; off <<= 1) {
            int nb = __shfl_up_sync(0xffffffffu, inc, off);
            if (lane >= off) inc += nb;
        }
        if (lane == 31) s_misc[8 + wid] = inc;
        __syncthreads();
        if (t < 32) {
            int w = (t < 16) ? s_misc[8 + t] : 0;
            int winc = w;
#pragma unroll
            for (int off = 1; off < 16; off <<= 1) {
                int nb = __shfl_up_sync(0xffffffffu, winc, off);
                if (t >= off) winc += nb;
            }
            if (t < 16) s_misc[8 + t] = winc - w;
        }
        __syncthreads();
        int off0 = s_misc[8 + wid] + (inc - run);
#pragma unroll
        for (int q = 0; q < PER; q++) {
            if (base + q < NCELL) s_hist[base + q] = off0;
            off0 += vals[q];
        }
    }
    __syncthreads();

    // ---- phase 3: scatter into transposed smem layout ----
    for (int i = t; i < NPTS; i += FPS_T) {
        float4 p = p4[i];
        int d = atomicAdd(&s_hist[mcell<GB>(p.x, p.y, p.z)], 1);
        int slot = (d & (PTS - 1)) * FPS_T + (d >> LOGP);
        px[slot] = p.x; py[slot] = p.y; pz[slot] = p.z;
        sori[d] = i;
        if (i == 0) s_misc[0] = d;
    }
    __syncthreads();

    // ---- phase 4: per-thread AABB + mind init ----
    float mind[PTS];
    float lox = CUDART_INF_F, loy = CUDART_INF_F, loz = CUDART_INF_F;
    float hix = -CUDART_INF_F, hiy = -CUDART_INF_F, hiz = -CUDART_INF_F;
#pragma unroll
    for (int k = 0; k < PTS; k++) {
        int slot = k * FPS_T + t;
        float X = px[slot], Y = py[slot], Z = pz[slot];
        lox = fminf(lox, X); hix = fmaxf(hix, X);
        loy = fminf(loy, Y); hiy = fmaxf(hiy, Y);
        loz = fminf(loz, Z); hiz = fmaxf(hiz, Z);
        mind[k] = CUDART_INF_F;
    }

    // persistent per-thread state: (chunk_val, chunk_si) is ALWAYS this
    // thread's own best pair — cached across skipped steps (R5 bug was
    // replacing chunk_si with a stale warp-level index).
    float chunk_val = CUDART_INF_F;
    int chunk_si = t * PTS;
    unsigned warp_val = __float_as_uint(CUDART_INF_F);
    int warp_si = t * PTS;
    int j = s_misc[0];
    if (t == 0) sel[0] = j;

    // ---- phase 5: the FPS scan ----
    for (int step = 1; step < M; ++step) {
        int slotj = (j & (PTS - 1)) * FPS_T + (j >> LOGP);
        float cx = px[slotj], cy = py[slotj], cz = pz[slotj];

        float ax = fmaxf(fmaxf(lox - cx, cx - hix), 0.0f);
        float ay = fmaxf(fmaxf(loy - cy, cy - hiy), 0.0f);
        float az = fmaxf(fmaxf(loz - cz, cz - hiz), 0.0f);
        float lb = fmaf(ax, ax, fmaf(ay, ay, az * az)) * 0.9999f;
        bool touch = lb < chunk_val;

        if (__ballot_sync(0xffffffffu, touch)) {
            if (touch) {
#pragma unroll
                for (int k = 0; k < PTS; k++) {
                    int slot = k * FPS_T + t;
                    float dx = __fadd_rn(px[slot], -cx);
                    float dy = __fadd_rn(py[slot], -cy);
                    float dz = __fadd_rn(pz[slot], -cz);
                    float d2 = __fadd_rn(__fadd_rn(__fmul_rn(dx, dx), __fmul_rn(dy, dy)),
                                         __fmul_rn(dz, dz));
                    mind[k] = fminf(mind[k], d2);
                }
                float red[PTS];
#pragma unroll
                for (int k = 0; k < PTS; k++) red[k] = mind[k];
#pragma unroll
                for (int w = PTS / 2; w >= 1; w >>= 1)
#pragma unroll
                    for (int k = 0; k < PTS / 2; k++)
                        if (k < w) red[k] = fmaxf(red[k], red[k + w]);
                float bv = red[0];
                unsigned msk = 0u;
#pragma unroll
                for (int k = 0; k < PTS; k++)
                    if (mind[k] == bv) msk |= (1u << k);
                chunk_val = bv;
                chunk_si = t * PTS + (__ffs(msk) - 1);
            }
            // warp reduce: hardware REDUX on positive-float bits
            unsigned mybits = __float_as_uint(chunk_val);
            unsigned wmax = __reduce_max_sync(0xffffffffu, mybits);
            unsigned who = __ballot_sync(0xffffffffu, mybits == wmax);
            int src = __ffs(who) - 1;
            warp_val = wmax;
            warp_si = __shfl_sync(0xffffffffu, chunk_si, src);
        }

        int par = (step & 1) << 4;
        if (lane == 0) { s_val[par + wid] = warp_val; s_si[par + wid] = warp_si; }
        __syncthreads();

        // block reduce: broadcast LDS of 16 warp maxima + REDUX
        unsigned v = s_val[par + (lane & 15)];
        unsigned bmax = __reduce_max_sync(0xffffffffu, v);
        unsigned wwin = __ballot_sync(0xffffffffu, v == bmax) & 0xffffu;
        int widwin = __ffs(wwin) - 1;
        j = s_si[par + widwin];
        if (t == 0) sel[step] = j;
    }

    // ---- phase 6: remap raw sorted indices to original indices ----
    __syncthreads();
    for (int i = t; i < M; i += FPS_T) {
        int si_ = sel[i];
        sel[i] = sori[si_];
    }
}

// ---------------- gather sampled positions ----------------
__global__ void gather_kernel(const float4* __restrict__ src, const int* __restrict__ sel,
                              float4* __restrict__ dst, int m) {
    int i = blockIdx.x * blockDim.x + threadIdx.x;
    if (i < m) dst[i] = src[sel[i]];
}

// ---------------- SA: radius group + PointConv + max-agg ----------------
template <int NSRC>
__global__ void sa_conv_kernel(const float4* __restrict__ p4s, const float4* __restrict__ p4t,
                               const float4* __restrict__ hs, float4* __restrict__ xt,
                               const float* __restrict__ W0, const float* __restrict__ b0,
                               const float* __restrict__ W1, const float* __restrict__ b1,
                               int ntgt) {
    __shared__ float sW0[19 * 19], sW1[19 * 16], sb0[19], sb1[16];
    int t = threadIdx.x;
    for (int i = t; i < 361; i += blockDim.x) sW0[i] = W0[i];
    for (int i = t; i < 304; i += blockDim.x) sW1[i] = W1[i];
    if (t < 19) sb0[t] = b0[t];
    if (t < 16) sb1[t] = b1[t];
    __syncthreads();

    int warp = (blockIdx.x * blockDim.x + t) >> 5;
    int lane = t & 31;
    if (warp >= ntgt) return;

    float4 pt = p4t[warp];
    float na = pt.w;
    float myd = 0.0f;
    int myj = 0;
    int cnt = 0;

    for (int base = 0; base < NSRC; base += 32) {
        int j = base + lane;
        float4 ps = p4s[j];
        float dot = fmaf(pt.x, ps.x, fmaf(pt.y, ps.y, pt.z * ps.z));
        float d2 = fmaxf((na + ps.w) - 2.0f * dot, 0.0f);
        bool hit = d2 <= R2C;
        unsigned mm = __ballot_sync(0xffffffffu, hit);
        while (mm) {
            int b = __ffs(mm) - 1;
            mm &= mm - 1;
            float nd = __shfl_sync(0xffffffffu, d2, b);
            int nj = base + b;
            if (cnt < 32) {
                if (lane == cnt) { myd = nd; myj = nj; }
                cnt++;
            } else {
                float mv = (lane < cnt) ? myd : -CUDART_INF_F;
                int ml = lane;
#pragma unroll
                for (int off = 16; off; off >>= 1) {
                    float ov = __shfl_xor_sync(0xffffffffu, mv, off);
                    int ol = __shfl_xor_sync(0xffffffffu, ml, off);
                    if (ov > mv) { mv = ov; ml = ol; }
                }
                if (nd < mv && lane == ml) { myd = nd; myj = nj; }
            }
        }
    }

    bool valid = lane < cnt;
    int jj = valid ? myj : 0;
    float in[19];
    load16(&hs[jj * 4], in);
    float4 sp = p4s[jj];
    in[16] = sp.x - pt.x;
    in[17] = sp.y - pt.y;
    in[18] = sp.z - pt.z;

    float hid[19];
#pragma unroll
    for (int o = 0; o < 19; o++) hid[o] = sb0[o];
#pragma unroll
    for (int i = 0; i < 19; i++) {
        float v = in[i];
#pragma unroll
        for (int o = 0; o < 19; o++) hid[o] = fmaf(v, sW0[i * 19 + o], hid[o]);
    }
#pragma unroll
    for (int o = 0; o < 19; o++) hid[o] = fmaxf(hid[o], 0.0f);

    float out[16];
#pragma unroll
    for (int o = 0; o < 16; o++) out[o] = sb1[o];
#pragma unroll
    for (int i = 0; i < 19; i++) {
        float v = hid[i];
#pragma unroll
        for (int o = 0; o < 16; o++) out[o] = fmaf(v, sW1[i * 16 + o], out[o]);
    }
    float res[16];
#pragma unroll
    for (int c = 0; c < 16; c++) {
        float r = valid ? fmaxf(out[c], 0.0f) : -CUDART_INF_F;
#pragma unroll
        for (int off = 16; off; off >>= 1) r = fmaxf(r, __shfl_xor_sync(0xffffffffu, r, off));
        res[c] = r;
    }
    if (lane == 0) store16(&xt[warp * 4], res);
}

// ---------------- FP: kNN(3) interpolate + MLP(32->32->16) ----------------
template <int NC>
__global__ void fp_kernel(const float4* __restrict__ p4f, const float4* __restrict__ p4c,
                          const float4* __restrict__ xc, const float4* __restrict__ xs,
                          float4* __restrict__ xf,
                          const float* __restrict__ W0, const float* __restrict__ b0,
                          const float* __restrict__ W1, const float* __restrict__ b1,
                          int nf) {
    __shared__ float sW0[32 * 32], sW1[32 * 16], sb0[32], sb1[16];
    int t = threadIdx.x;
    for (int i = t; i < 1024; i += blockDim.x) sW0[i] = W0[i];
    for (int i = t; i < 512; i += blockDim.x) sW1[i] = W1[i];
    if (t < 32) sb0[t] = b0[t];
    if (t < 16) sb1[t] = b1[t];
    __syncthreads();

    int g = blockIdx.x * blockDim.x + t;
    if (g >= nf) return;
    float4 f = p4f[g];
    float na = f.w;
    float d0 = CUDART_INF_F, d1 = CUDART_INF_F, d2 = CUDART_INF_F;
    int i0 = 0, i1 = 0, i2 = 0;
    for (int j = 0; j < NC; j++) {
        float4 c = p4c[j];
        float dot = fmaf(f.x, c.x, fmaf(f.y, c.y, f.z * c.z));
        float dd = fmaxf((na + c.w) - 2.0f * dot, 0.0f);
        if (dd < d0) {
            d2 = d1; i2 = i1; d1 = d0; i1 = i0; d0 = dd; i0 = j;
        } else if (dd < d1) {
            d2 = d1; i2 = i1; d1 = dd; i1 = j;
        } else if (dd < d2) {
            d2 = dd; i2 = j;
        }
    }
    float w0 = 1.0f / fmaxf(d0, 1e-16f);
    float w1 = 1.0f / fmaxf(d1, 1e-16f);
    float w2 = 1.0f / fmaxf(d2, 1e-16f);
    float ws = w0 + w1 + w2;
    w0 /= ws; w1 /= ws; w2 /= ws;

    float a0[16], a1[16], a2[16], in[32];
    load16(&xc[i0 * 4], a0);
    load16(&xc[i1 * 4], a1);
    load16(&xc[i2 * 4], a2);
#pragma unroll
    for (int c = 0; c < 16; c++) in[c] = (a0[c] * w0 + a1[c] * w1) + a2[c] * w2;
    load16(&xs[g * 4], in + 16);

    float hid[32];
#pragma unroll
    for (int o = 0; o < 32; o++) hid[o] = sb0[o];
#pragma unroll
    for (int i = 0; i < 32; i++) {
        float v = in[i];
#pragma unroll
        for (int o = 0; o < 32; o++) hid[o] = fmaf(v, sW0[i * 32 + o], hid[o]);
    }
#pragma unroll
    for (int o = 0; o < 32; o++) hid[o] = fmaxf(hid[o], 0.0f);
    float out[16];
#pragma unroll
    for (int o = 0; o < 16; o++) out[o] = sb1[o];
#pragma unroll
    for (int i = 0; i < 32; i++) {
        float v = hid[i];
#pragma unroll
        for (int o = 0; o < 16; o++) out[o] = fmaf(v, sW1[i * 16 + o], out[o]);
    }
#pragma unroll
    for (int o = 0; o < 16; o++) out[o] = fmaxf(out[o], 0.0f);
    store16(&xf[g * 4], out);
}

// ---------------- lin_out ----------------
__global__ void lin_out_kernel(const float* __restrict__ W0, const float* __restrict__ b0,
                               const float* __restrict__ W1, const float* __restrict__ b1,
                               float* __restrict__ out) {
    __shared__ float sW0[256], sW1[32], sb0[16], sb1[2];
    int t = threadIdx.x;
    for (int i = t; i < 256; i += blockDim.x) sW0[i] = W0[i];
    if (t < 32) sW1[t] = W1[t];
    if (t < 16) sb0[t] = b0[t];
    if (t < 2) sb1[t] = b1[t];
    __syncthreads();
    int g = blockIdx.x * blockDim.x + t;
    if (g >= N0) return;
    float in[16], hid[16];
    load16(&g_f0[g * 4], in);
#pragma unroll
    for (int o = 0; o < 16; o++) hid[o] = sb0[o];
#pragma unroll
    for (int i = 0; i < 16; i++) {
        float v = in[i];
#pragma unroll
        for (int o = 0; o < 16; o++) hid[o] = fmaf(v, sW0[i * 16 + o], hid[o]);
    }
    float o0 = sb1[0], o1 = sb1[1];
#pragma unroll
    for (int i = 0; i < 16; i++) {
        float v = fmaxf(hid[i], 0.0f);
        o0 = fmaf(v, sW1[i * 2 + 0], o0);
        o1 = fmaf(v, sW1[i * 2 + 1], o1);
    }
    out[g * 2 + 0] = o0;
    out[g * 2 + 1] = o1;
}

// ---------------- host launcher ----------------
extern "C" void kernel_launch(void* const* d_in, const int* in_sizes, int n_in,
                              void* d_out, int out_size) {
    const float* x = (const float*)d_in[0];
    const float* pos = (const float*)d_in[1];
    const float* liW0 = (const float*)d_in[3];
    const float* lib0 = (const float*)d_in[4];
    const float* liW1 = (const float*)d_in[5];
    const float* lib1 = (const float*)d_in[6];
    const float* saW0 = (const float*)d_in[7];
    const float* sab0 = (const float*)d_in[8];
    const float* saW1 = (const float*)d_in[9];
    const float* sab1 = (const float*)d_in[10];
    const float* fpW0 = (const float*)d_in[11];
    const float* fpb0 = (const float*)d_in[12];
    const float* fpW1 = (const float*)d_in[13];
    const float* fpb1 = (const float*)d_in[14];
    const float* loW0 = (const float*)d_in[15];
    const float* lob0 = (const float*)d_in[16];
    const float* loW1 = (const float*)d_in[17];
    const float* lob1 = (const float*)d_in[18];
    float* out = (float*)d_out;

    void *p40, *p41, *p42, *p43, *s0, *s1, *s2, *sori, *h0, *x1, *x2, *x3, *f2, *f1, *f0;
    cudaGetSymbolAddress(&p40, g_p4_0);
    cudaGetSymbolAddress(&p41, g_p4_1);
    cudaGetSymbolAddress(&p42, g_p4_2);
    cudaGetSymbolAddress(&p43, g_p4_3);
    cudaGetSymbolAddress(&s0, g_sel0);
    cudaGetSymbolAddress(&s1, g_sel1);
    cudaGetSymbolAddress(&s2, g_sel2);
    cudaGetSymbolAddress(&sori, g_sori);
    cudaGetSymbolAddress(&h0, g_h0);
    cudaGetSymbolAddress(&x1, g_x1);
    cudaGetSymbolAddress(&x2, g_x2);
    cudaGetSymbolAddress(&x3, g_x3);
    cudaGetSymbolAddress(&f2, g_f2);
    cudaGetSymbolAddress(&f1, g_f1);
    cudaGetSymbolAddress(&f0, g_f0);

    size_t sm0 = (size_t)N0 * 12;
    size_t sm1 = (size_t)N1 * 12;
    size_t sm2 = (size_t)N2 * 12;
    cudaFuncSetAttribute((const void*)fps_kernel<N0, N1, 32, 4>,
                         cudaFuncAttributeMaxDynamicSharedMemorySize, (int)sm0);
    cudaFuncSetAttribute((const void*)fps_kernel<N1, N2, 16, 3>,
                         cudaFuncAttributeMaxDynamicSharedMemorySize, (int)sm1);
    cudaFuncSetAttribute((const void*)fps_kernel<N2, N3, 8, 3>,
                         cudaFuncAttributeMaxDynamicSharedMemorySize, (int)sm2);

    prep_kernel<<<(N0 + 255) / 256, 256>>>(pos);
    lin_in_kernel<<<N0 / 128, 128>>>(x, liW0, lib0, liW1, lib1);

    // level 0
    fps_kernel<N0, N1, 32, 4><<<1, FPS_T, sm0>>>((const float4*)p40, (int*)s0, (int*)sori);
    gather_kernel<<<N1 / 256, 256>>>((const float4*)p40, (const int*)s0, (float4*)p41, N1);
    sa_conv_kernel<N0><<<N1 * 32 / 256, 256>>>((const float4*)p40, (const float4*)p41,
                                               (const float4*)h0, (float4*)x1,
                                               saW0, sab0, saW1, sab1, N1);
    // level 1
    fps_kernel<N1, N2, 16, 3><<<1, FPS_T, sm1>>>((const float4*)p41, (int*)s1, (int*)sori);
    gather_kernel<<<N2 / 256, 256>>>((const float4*)p41, (const int*)s1, (float4*)p42, N2);
    sa_conv_kernel<N1><<<N2 * 32 / 256, 256>>>((const float4*)p41, (const float4*)p42,
                                               (const float4*)x1, (float4*)x2,
                                               saW0 + 361, sab0 + 19, saW1 + 304, sab1 + 16, N2);
    // level 2
    fps_kernel<N2, N3, 8, 3><<<1, FPS_T, sm2>>>((const float4*)p42, (int*)s2, (int*)sori);
    gather_kernel<<<N3 / 256, 256>>>((const float4*)p42, (const int*)s2, (float4*)p43, N3);
    sa_conv_kernel<N2><<<N3 * 32 / 256, 256>>>((const float4*)p42, (const float4*)p43,
                                               (const float4*)x2, (float4*)x3,
                                               saW0 + 722, sab0 + 38, saW1 + 608, sab1 + 32, N3);

    // FP path (coarse -> fine)
    fp_kernel<N3><<<N2 / 128, 128>>>((const float4*)p42, (const float4*)p43,
                                     (const float4*)x3, (const float4*)x2, (float4*)f2,
                                     fpW0 + 2 * 1024, fpb0 + 2 * 32, fpW1 + 2 * 512, fpb1 + 2 * 16,
                                     N2);
    fp_kernel<N2><<<N1 / 128, 128>>>((const float4*)p41, (const float4*)p42,
                                     (const float4*)f2, (const float4*)x1, (float4*)f1,
                                     fpW0 + 1024, fpb0 + 32, fpW1 + 512, fpb1 + 16, N1);
    fp_kernel<N1><<<N0 / 128, 128>>>((const float4*)p40, (const float4*)p41,
                                     (const float4*)f1, (const float4*)h0, (float4*)f0,
                                     fpW0, fpb0, fpW1, fpb1, N0);

    lin_out_kernel<<<N0 / 256, 256>>>(loW0, lob0, loW1, lob1, out);
}

// round 8
// speedup vs baseline: 2.0266x; 1.0471x over previous
#include <cuda_runtime.h>
#include <math_constants.h>

#define N0 16384
#define N1 8192
#define N2 4096
#define N3 2048
#define R2C 4.0f
#define FPS_T 1024

// ---------------- device scratch (no allocations allowed) ----------------
__device__ float4 g_p4_0[N0];
__device__ float4 g_p4_1[N1];
__device__ float4 g_p4_2[N2];
__device__ float4 g_p4_3[N3];
__device__ int    g_sel0[N1];
__device__ int    g_sel1[N2];
__device__ int    g_sel2[N3];
__device__ int    g_sori[N0];     // per-level sorted->original index scratch
__device__ float4 g_h0[N0 * 4];   // 16 floats per point
__device__ float4 g_x1[N1 * 4];
__device__ float4 g_x2[N2 * 4];
__device__ float4 g_x3[N3 * 4];
__device__ float4 g_f2[N2 * 4];
__device__ float4 g_f1[N1 * 4];
__device__ float4 g_f0[N0 * 4];

// ---------------- prep: pack pos + squared norm into float4 ----------------
__global__ void prep_kernel(const float* __restrict__ pos) {
    int i = blockIdx.x * blockDim.x + threadIdx.x;
    if (i >= N0) return;
    float x = pos[3 * i], y = pos[3 * i + 1], z = pos[3 * i + 2];
    float nb = __fadd_rn(__fadd_rn(__fmul_rn(x, x), __fmul_rn(y, y)), __fmul_rn(z, z));
    g_p4_0[i] = make_float4(x, y, z, nb);
}

__device__ __forceinline__ void load16(const float4* __restrict__ row, float* v) {
    float4 a = row[0], b = row[1], c = row[2], d = row[3];
    v[0] = a.x; v[1] = a.y; v[2] = a.z; v[3] = a.w;
    v[4] = b.x; v[5] = b.y; v[6] = b.z; v[7] = b.w;
    v[8] = c.x; v[9] = c.y; v[10] = c.z; v[11] = c.w;
    v[12] = d.x; v[13] = d.y; v[14] = d.z; v[15] = d.w;
}

__device__ __forceinline__ void store16(float4* __restrict__ row, const float* v) {
    row[0] = make_float4(v[0], v[1], v[2], v[3]);
    row[1] = make_float4(v[4], v[5], v[6], v[7]);
    row[2] = make_float4(v[8], v[9], v[10], v[11]);
    row[3] = make_float4(v[12], v[13], v[14], v[15]);
}

// ---------------- lin_in ----------------
__global__ void lin_in_kernel(const float* __restrict__ x,
                              const float* __restrict__ W0, const float* __restrict__ b0,
                              const float* __restrict__ W1, const float* __restrict__ b1) {
    __shared__ float sW0[256], sW1[256], sb0[16], sb1[16];
    int t = threadIdx.x;
    for (int i = t; i < 256; i += blockDim.x) { sW0[i] = W0[i]; sW1[i] = W1[i]; }
    if (t < 16) { sb0[t] = b0[t]; sb1[t] = b1[t]; }
    __syncthreads();
    int g = blockIdx.x * blockDim.x + t;
    if (g >= N0) return;
    float in[16], hid[16], out[16];
    load16((const float4*)(x + g * 16), in);
#pragma unroll
    for (int o = 0; o < 16; o++) hid[o] = sb0[o];
#pragma unroll
    for (int i = 0; i < 16; i++) {
        float v = in[i];
#pragma unroll
        for (int o = 0; o < 16; o++) hid[o] = fmaf(v, sW0[i * 16 + o], hid[o]);
    }
#pragma unroll
    for (int o = 0; o < 16; o++) hid[o] = fmaxf(hid[o], 0.0f);
#pragma unroll
    for (int o = 0; o < 16; o++) out[o] = sb1[o];
#pragma unroll
    for (int i = 0; i < 16; i++) {
        float v = hid[i];
#pragma unroll
        for (int o = 0; o < 16; o++) out[o] = fmaf(v, sW1[i * 16 + o], out[o]);
    }
#pragma unroll
    for (int o = 0; o < 16; o++) out[o] = fmaxf(out[o], 0.0f);
    store16(&g_h0[g * 4], out);
}

// ---------------- FPS with spatial sort + AABB pruning + REDUX argmax ----------------
template <int GB>
__device__ __forceinline__ int mcell(float x, float y, float z) {
    const float inv = (float)(1 << GB) * (1.0f / 32.0f);
    int cx = min((1 << GB) - 1, max(0, (int)(x * inv)));
    int cy = min((1 << GB) - 1, max(0, (int)(y * inv)));
    int cz = min((1 << GB) - 1, max(0, (int)(z * inv)));
    int m = 0;
#pragma unroll
    for (int b = 0; b < GB; b++)
        m |= (((cx >> b) & 1) << (3 * b)) | (((cy >> b) & 1) << (3 * b + 1)) |
             (((cz >> b) & 1) << (3 * b + 2));
    return m;
}

// NPTS points, select M, PTS = NPTS/1024 points per thread, GB grid bits per dim
template <int NPTS, int M, int PTS, int GB>
__global__ __launch_bounds__(FPS_T, 1)
void fps_kernel(const float4* __restrict__ p4, int* __restrict__ sel, int* __restrict__ sori) {
    constexpr int NCELL = 1 << (3 * GB);
    constexpr int LOGP = (PTS == 16) ? 4 : (PTS == 8) ? 3 : 2;
    __shared__ int s_hist[4096];
    __shared__ unsigned s_val[64];   // [2 parities][32 warps]
    __shared__ int s_si[64];
    __shared__ int s_misc[40];

    extern __shared__ float sm[];
    float* px = sm;
    float* py = sm + NPTS;
    float* pz = sm + 2 * NPTS;

    const int t = threadIdx.x;
    const int lane = t & 31;
    const int wid = t >> 5;

    // ---- phase 1: histogram ----
    for (int i = t; i < NCELL; i += FPS_T) s_hist[i] = 0;
    __syncthreads();
    for (int i = t; i < NPTS; i += FPS_T) {
        float4 p = p4[i];
        atomicAdd(&s_hist[mcell<GB>(p.x, p.y, p.z)], 1);
    }
    __syncthreads();

    // ---- phase 2: exclusive block scan of s_hist[0..NCELL) ----
    {
        constexpr int PER = (NCELL + FPS_T - 1) / FPS_T;
        int base = t * PER;
        int vals[PER];
        int run = 0;
#pragma unroll
        for (int q = 0; q < PER; q++) {
            int v = (base + q < NCELL) ? s_hist[base + q] : 0;
            vals[q] = v;
            run += v;
        }
        int inc = run;
#pragma unroll
        for (int off = 1; off < 32; off <<= 1) {
            int nb = __shfl_up_sync(0xffffffffu, inc, off);
            if (lane >= off) inc += nb;
        }
        if (lane == 31) s_misc[8 + wid] = inc;
        __syncthreads();
        if (t < 32) {
            int w = s_misc[8 + t];
            int winc = w;
#pragma unroll
            for (int off = 1; off < 32; off <<= 1) {
                int nb = __shfl_up_sync(0xffffffffu, winc, off);
                if (t >= off) winc += nb;
            }
            s_misc[8 + t] = winc - w;
        }
        __syncthreads();
        int off0 = s_misc[8 + wid] + (inc - run);
#pragma unroll
        for (int q = 0; q < PER; q++) {
            if (base + q < NCELL) s_hist[base + q] = off0;
            off0 += vals[q];
        }
    }
    __syncthreads();

    // ---- phase 3: scatter into transposed smem layout ----
    for (int i = t; i < NPTS; i += FPS_T) {
        float4 p = p4[i];
        int d = atomicAdd(&s_hist[mcell<GB>(p.x, p.y, p.z)], 1);
        int slot = (d & (PTS - 1)) * FPS_T + (d >> LOGP);
        px[slot] = p.x; py[slot] = p.y; pz[slot] = p.z;
        sori[d] = i;
        if (i == 0) s_misc[0] = d;
    }
    __syncthreads();

    // ---- phase 4: per-thread AABB + mind init ----
    float mind[PTS];
    float lox = CUDART_INF_F, loy = CUDART_INF_F, loz = CUDART_INF_F;
    float hix = -CUDART_INF_F, hiy = -CUDART_INF_F, hiz = -CUDART_INF_F;
#pragma unroll
    for (int k = 0; k < PTS; k++) {
        int slot = k * FPS_T + t;
        float X = px[slot], Y = py[slot], Z = pz[slot];
        lox = fminf(lox, X); hix = fmaxf(hix, X);
        loy = fminf(loy, Y); hiy = fmaxf(hiy, Y);
        loz = fminf(loz, Z); hiz = fmaxf(hiz, Z);
        mind[k] = CUDART_INF_F;
    }

    // persistent per-thread state: (chunk_val, chunk_si) is ALWAYS this
    // thread's own best pair — cached across skipped steps.
    float chunk_val = CUDART_INF_F;
    int chunk_si = t * PTS;
    unsigned warp_val = __float_as_uint(CUDART_INF_F);
    int warp_si = t * PTS;
    int j = s_misc[0];
    if (t == 0) sel[0] = j;

    // ---- phase 5: the FPS scan ----
    for (int step = 1; step < M; ++step) {
        int slotj = (j & (PTS - 1)) * FPS_T + (j >> LOGP);
        float cx = px[slotj], cy = py[slotj], cz = pz[slotj];

        float ax = fmaxf(fmaxf(lox - cx, cx - hix), 0.0f);
        float ay = fmaxf(fmaxf(loy - cy, cy - hiy), 0.0f);
        float az = fmaxf(fmaxf(loz - cz, cz - hiz), 0.0f);
        float lb = fmaf(ax, ax, fmaf(ay, ay, az * az)) * 0.9999f;
        bool touch = lb < chunk_val;

        if (__ballot_sync(0xffffffffu, touch)) {
            if (touch) {
#pragma unroll
                for (int k = 0; k < PTS; k++) {
                    int slot = k * FPS_T + t;
                    float dx = __fadd_rn(px[slot], -cx);
                    float dy = __fadd_rn(py[slot], -cy);
                    float dz = __fadd_rn(pz[slot], -cz);
                    float d2 = __fadd_rn(__fadd_rn(__fmul_rn(dx, dx), __fmul_rn(dy, dy)),
                                         __fmul_rn(dz, dz));
                    mind[k] = fminf(mind[k], d2);
                }
                float red[PTS];
#pragma unroll
                for (int k = 0; k < PTS; k++) red[k] = mind[k];
#pragma unroll
                for (int w = PTS / 2; w >= 1; w >>= 1)
#pragma unroll
                    for (int k = 0; k < PTS / 2; k++)
                        if (k < w) red[k] = fmaxf(red[k], red[k + w]);
                float bv = red[0];
                unsigned msk = 0u;
#pragma unroll
                for (int k = 0; k < PTS; k++)
                    if (mind[k] == bv) msk |= (1u << k);
                chunk_val = bv;
                chunk_si = t * PTS + (__ffs(msk) - 1);
            }
            // warp reduce: hardware REDUX on positive-float bits
            unsigned mybits = __float_as_uint(chunk_val);
            unsigned wmax = __reduce_max_sync(0xffffffffu, mybits);
            unsigned who = __ballot_sync(0xffffffffu, mybits == wmax);
            int src = __ffs(who) - 1;
            warp_val = wmax;
            warp_si = __shfl_sync(0xffffffffu, chunk_si, src);
        }

        int par = (step & 1) << 5;
        if (lane == 0) { s_val[par + wid] = warp_val; s_si[par + wid] = warp_si; }
        __syncthreads();

        // block reduce: broadcast LDS of 32 warp maxima + REDUX
        unsigned v = s_val[par + lane];
        unsigned bmax = __reduce_max_sync(0xffffffffu, v);
        unsigned wwin = __ballot_sync(0xffffffffu, v == bmax);
        int widwin = __ffs(wwin) - 1;
        j = s_si[par + widwin];
        if (t == 0) sel[step] = j;
    }

    // ---- phase 6: remap raw sorted indices to original indices ----
    __syncthreads();
    for (int i = t; i < M; i += FPS_T) {
        int si_ = sel[i];
        sel[i] = sori[si_];
    }
}

// ---------------- gather sampled positions ----------------
__global__ void gather_kernel(const float4* __restrict__ src, const int* __restrict__ sel,
                              float4* __restrict__ dst, int m) {
    int i = blockIdx.x * blockDim.x + threadIdx.x;
    if (i < m) dst[i] = src[sel[i]];
}

// ---------------- SA: radius group + PointConv + max-agg ----------------
template <int NSRC>
__global__ void sa_conv_kernel(const float4* __restrict__ p4s, const float4* __restrict__ p4t,
                               const float4* __restrict__ hs, float4* __restrict__ xt,
                               const float* __restrict__ W0, const float* __restrict__ b0,
                               const float* __restrict__ W1, const float* __restrict__ b1,
                               int ntgt) {
    __shared__ float sW0[19 * 19], sW1[19 * 16], sb0[19], sb1[16];
    int t = threadIdx.x;
    for (int i = t; i < 361; i += blockDim.x) sW0[i] = W0[i];
    for (int i = t; i < 304; i += blockDim.x) sW1[i] = W1[i];
    if (t < 19) sb0[t] = b0[t];
    if (t < 16) sb1[t] = b1[t];
    __syncthreads();

    int warp = (blockIdx.x * blockDim.x + t) >> 5;
    int lane = t & 31;
    if (warp >= ntgt) return;

    float4 pt = p4t[warp];
    float na = pt.w;
    float myd = 0.0f;
    int myj = 0;
    int cnt = 0;

    for (int base = 0; base < NSRC; base += 32) {
        int j = base + lane;
        float4 ps = p4s[j];
        float dot = fmaf(pt.x, ps.x, fmaf(pt.y, ps.y, pt.z * ps.z));
        float d2 = fmaxf((na + ps.w) - 2.0f * dot, 0.0f);
        bool hit = d2 <= R2C;
        unsigned mm = __ballot_sync(0xffffffffu, hit);
        while (mm) {
            int b = __ffs(mm) - 1;
            mm &= mm - 1;
            float nd = __shfl_sync(0xffffffffu, d2, b);
            int nj = base + b;
            if (cnt < 32) {
                if (lane == cnt) { myd = nd; myj = nj; }
                cnt++;
            } else {
                float mv = (lane < cnt) ? myd : -CUDART_INF_F;
                int ml = lane;
#pragma unroll
                for (int off = 16; off; off >>= 1) {
                    float ov = __shfl_xor_sync(0xffffffffu, mv, off);
                    int ol = __shfl_xor_sync(0xffffffffu, ml, off);
                    if (ov > mv) { mv = ov; ml = ol; }
                }
                if (nd < mv && lane == ml) { myd = nd; myj = nj; }
            }
        }
    }

    bool valid = lane < cnt;
    int jj = valid ? myj : 0;
    float in[19];
    load16(&hs[jj * 4], in);
    float4 sp = p4s[jj];
    in[16] = sp.x - pt.x;
    in[17] = sp.y - pt.y;
    in[18] = sp.z - pt.z;

    float hid[19];
#pragma unroll
    for (int o = 0; o < 19; o++) hid[o] = sb0[o];
#pragma unroll
    for (int i = 0; i < 19; i++) {
        float v = in[i];
#pragma unroll
        for (int o = 0; o < 19; o++) hid[o] = fmaf(v, sW0[i * 19 + o], hid[o]);
    }
#pragma unroll
    for (int o = 0; o < 19; o++) hid[o] = fmaxf(hid[o], 0.0f);

    float out[16];
#pragma unroll
    for (int o = 0; o < 16; o++) out[o] = sb1[o];
#pragma unroll
    for (int i = 0; i < 19; i++) {
        float v = hid[i];
#pragma unroll
        for (int o = 0; o < 16; o++) out[o] = fmaf(v, sW1[i * 16 + o], out[o]);
    }
    float res[16];
#pragma unroll
    for (int c = 0; c < 16; c++) {
        float r = valid ? fmaxf(out[c], 0.0f) : -CUDART_INF_F;
#pragma unroll
        for (int off = 16; off; off >>= 1) r = fmaxf(r, __shfl_xor_sync(0xffffffffu, r, off));
        res[c] = r;
    }
    if (lane == 0) store16(&xt[warp * 4], res);
}

// ---------------- FP: kNN(3) interpolate + MLP(32->32->16) ----------------
template <int NC>
__global__ void fp_kernel(const float4* __restrict__ p4f, const float4* __restrict__ p4c,
                          const float4* __restrict__ xc, const float4* __restrict__ xs,
                          float4* __restrict__ xf,
                          const float* __restrict__ W0, const float* __restrict__ b0,
                          const float* __restrict__ W1, const float* __restrict__ b1,
                          int nf) {
    __shared__ float sW0[32 * 32], sW1[32 * 16], sb0[32], sb1[16];
    int t = threadIdx.x;
    for (int i = t; i < 1024; i += blockDim.x) sW0[i] = W0[i];
    for (int i = t; i < 512; i += blockDim.x) sW1[i] = W1[i];
    if (t < 32) sb0[t] = b0[t];
    if (t < 16) sb1[t] = b1[t];
    __syncthreads();

    int g = blockIdx.x * blockDim.x + t;
    if (g >= nf) return;
    float4 f = p4f[g];
    float na = f.w;
    float d0 = CUDART_INF_F, d1 = CUDART_INF_F, d2 = CUDART_INF_F;
    int i0 = 0, i1 = 0, i2 = 0;
    for (int j = 0; j < NC; j++) {
        float4 c = p4c[j];
        float dot = fmaf(f.x, c.x, fmaf(f.y, c.y, f.z * c.z));
        float dd = fmaxf((na + c.w) - 2.0f * dot, 0.0f);
        if (dd < d0) {
            d2 = d1; i2 = i1; d1 = d0; i1 = i0; d0 = dd; i0 = j;
        } else if (dd < d1) {
            d2 = d1; i2 = i1; d1 = dd; i1 = j;
        } else if (dd < d2) {
            d2 = dd; i2 = j;
        }
    }
    float w0 = 1.0f / fmaxf(d0, 1e-16f);
    float w1 = 1.0f / fmaxf(d1, 1e-16f);
    float w2 = 1.0f / fmaxf(d2, 1e-16f);
    float ws = w0 + w1 + w2;
    w0 /= ws; w1 /= ws; w2 /= ws;

    float a0[16], a1[16], a2[16], in[32];
    load16(&xc[i0 * 4], a0);
    load16(&xc[i1 * 4], a1);
    load16(&xc[i2 * 4], a2);
#pragma unroll
    for (int c = 0; c < 16; c++) in[c] = (a0[c] * w0 + a1[c] * w1) + a2[c] * w2;
    load16(&xs[g * 4], in + 16);

    float hid[32];
#pragma unroll
    for (int o = 0; o < 32; o++) hid[o] = sb0[o];
#pragma unroll
    for (int i = 0; i < 32; i++) {
        float v = in[i];
#pragma unroll
        for (int o = 0; o < 32; o++) hid[o] = fmaf(v, sW0[i * 32 + o], hid[o]);
    }
#pragma unroll
    for (int o = 0; o < 32; o++) hid[o] = fmaxf(hid[o], 0.0f);
    float out[16];
#pragma unroll
    for (int o = 0; o < 16; o++) out[o] = sb1[o];
#pragma unroll
    for (int i = 0; i < 32; i++) {
        float v = hid[i];
#pragma unroll
        for (int o = 0; o < 16; o++) out[o] = fmaf(v, sW1[i * 16 + o], out[o]);
    }
#pragma unroll
    for (int o = 0; o < 16; o++) out[o] = fmaxf(out[o], 0.0f);
    store16(&xf[g * 4], out);
}

// ---------------- lin_out ----------------
__global__ void lin_out_kernel(const float* __restrict__ W0, const float* __restrict__ b0,
                               const float* __restrict__ W1, const float* __restrict__ b1,
                               float* __restrict__ out) {
    __shared__ float sW0[256], sW1[32], sb0[16], sb1[2];
    int t = threadIdx.x;
    for (int i = t; i < 256; i += blockDim.x) sW0[i] = W0[i];
    if (t < 32) sW1[t] = W1[t];
    if (t < 16) sb0[t] = b0[t];
    if (t < 2) sb1[t] = b1[t];
    __syncthreads();
    int g = blockIdx.x * blockDim.x + t;
    if (g >= N0) return;
    float in[16], hid[16];
    load16(&g_f0[g * 4], in);
#pragma unroll
    for (int o = 0; o < 16; o++) hid[o] = sb0[o];
#pragma unroll
    for (int i = 0; i < 16; i++) {
        float v = in[i];
#pragma unroll
        for (int o = 0; o < 16; o++) hid[o] = fmaf(v, sW0[i * 16 + o], hid[o]);
    }
    float o0 = sb1[0], o1 = sb1[1];
#pragma unroll
    for (int i = 0; i < 16; i++) {
        float v = fmaxf(hid[i], 0.0f);
        o0 = fmaf(v, sW1[i * 2 + 0], o0);
        o1 = fmaf(v, sW1[i * 2 + 1], o1);
    }
    out[g * 2 + 0] = o0;
    out[g * 2 + 1] = o1;
}

// ---------------- host launcher ----------------
extern "C" void kernel_launch(void* const* d_in, const int* in_sizes, int n_in,
                              void* d_out, int out_size) {
    const float* x = (const float*)d_in[0];
    const float* pos = (const float*)d_in[1];
    const float* liW0 = (const float*)d_in[3];
    const float* lib0 = (const float*)d_in[4];
    const float* liW1 = (const float*)d_in[5];
    const float* lib1 = (const float*)d_in[6];
    const float* saW0 = (const float*)d_in[7];
    const float* sab0 = (const float*)d_in[8];
    const float* saW1 = (const float*)d_in[9];
    const float* sab1 = (const float*)d_in[10];
    const float* fpW0 = (const float*)d_in[11];
    const float* fpb0 = (const float*)d_in[12];
    const float* fpW1 = (const float*)d_in[13];
    const float* fpb1 = (const float*)d_in[14];
    const float* loW0 = (const float*)d_in[15];
    const float* lob0 = (const float*)d_in[16];
    const float* loW1 = (const float*)d_in[17];
    const float* lob1 = (const float*)d_in[18];
    float* out = (float*)d_out;

    void *p40, *p41, *p42, *p43, *s0, *s1, *s2, *sori, *h0, *x1, *x2, *x3, *f2, *f1, *f0;
    cudaGetSymbolAddress(&p40, g_p4_0);
    cudaGetSymbolAddress(&p41, g_p4_1);
    cudaGetSymbolAddress(&p42, g_p4_2);
    cudaGetSymbolAddress(&p43, g_p4_3);
    cudaGetSymbolAddress(&s0, g_sel0);
    cudaGetSymbolAddress(&s1, g_sel1);
    cudaGetSymbolAddress(&s2, g_sel2);
    cudaGetSymbolAddress(&sori, g_sori);
    cudaGetSymbolAddress(&h0, g_h0);
    cudaGetSymbolAddress(&x1, g_x1);
    cudaGetSymbolAddress(&x2, g_x2);
    cudaGetSymbolAddress(&x3, g_x3);
    cudaGetSymbolAddress(&f2, g_f2);
    cudaGetSymbolAddress(&f1, g_f1);
    cudaGetSymbolAddress(&f0, g_f0);

    size_t sm0 = (size_t)N0 * 12;
    size_t sm1 = (size_t)N1 * 12;
    size_t sm2 = (size_t)N2 * 12;
    cudaFuncSetAttribute((const void*)fps_kernel<N0, N1, 16, 4>,
                         cudaFuncAttributeMaxDynamicSharedMemorySize, (int)sm0);
    cudaFuncSetAttribute((const void*)fps_kernel<N1, N2, 8, 3>,
                         cudaFuncAttributeMaxDynamicSharedMemorySize, (int)sm1);
    cudaFuncSetAttribute((const void*)fps_kernel<N2, N3, 4, 3>,
                         cudaFuncAttributeMaxDynamicSharedMemorySize, (int)sm2);

    prep_kernel<<<(N0 + 255) / 256, 256>>>(pos);
    lin_in_kernel<<<N0 / 128, 128>>>(x, liW0, lib0, liW1, lib1);

    // level 0
    fps_kernel<N0, N1, 16, 4><<<1, FPS_T, sm0>>>((const float4*)p40, (int*)s0, (int*)sori);
    gather_kernel<<<N1 / 256, 256>>>((const float4*)p40, (const int*)s0, (float4*)p41, N1);
    sa_conv_kernel<N0><<<N1 * 32 / 256, 256>>>((const float4*)p40, (const float4*)p41,
                                               (const float4*)h0, (float4*)x1,
                                               saW0, sab0, saW1, sab1, N1);
    // level 1
    fps_kernel<N1, N2, 8, 3><<<1, FPS_T, sm1>>>((const float4*)p41, (int*)s1, (int*)sori);
    gather_kernel<<<N2 / 256, 256>>>((const float4*)p41, (const int*)s1, (float4*)p42, N2);
    sa_conv_kernel<N1><<<N2 * 32 / 256, 256>>>((const float4*)p41, (const float4*)p42,
                                               (const float4*)x1, (float4*)x2,
                                               saW0 + 361, sab0 + 19, saW1 + 304, sab1 + 16, N2);
    // level 2
    fps_kernel<N2, N3, 4, 3><<<1, FPS_T, sm2>>>((const float4*)p42, (int*)s2, (int*)sori);
    gather_kernel<<<N3 / 256, 256>>>((const float4*)p42, (const int*)s2, (float4*)p43, N3);
    sa_conv_kernel<N2><<<N3 * 32 / 256, 256>>>((const float4*)p42, (const float4*)p43,
                                               (const float4*)x2, (float4*)x3,
                                               saW0 + 722, sab0 + 38, saW1 + 608, sab1 + 32, N3);

    // FP path (coarse -> fine)
    fp_kernel<N3><<<N2 / 128, 128>>>((const float4*)p42, (const float4*)p43,
                                     (const float4*)x3, (const float4*)x2, (float4*)f2,
                                     fpW0 + 2 * 1024, fpb0 + 2 * 32, fpW1 + 2 * 512, fpb1 + 2 * 16,
                                     N2);
    fp_kernel<N2><<<N1 / 128, 128>>>((const float4*)p41, (const float4*)p42,
                                     (const float4*)f2, (const float4*)x1, (float4*)f1,
                                     fpW0 + 1024, fpb0 + 32, fpW1 + 512, fpb1 + 16, N1);
    fp_kernel<N1><<<N0 / 128, 128>>>((const float4*)p40, (const float4*)p41,
                                     (const float4*)f1, (const float4*)h0, (float4*)f0,
                                     fpW0, fpb0, fpW1, fpb1, N0);

    lin_out_kernel<<<N0 / 256, 256>>>(loW0, lob0, loW1, lob1, out);
}

// round 9
// speedup vs baseline: 2.1996x; 1.0854x over previous
#include <cuda_runtime.h>
#include <math_constants.h>

#define N0 16384
#define N1 8192
#define N2 4096
#define N3 2048
#define R2C 4.0f
#define FPS_T 1024

// ---------------- device scratch (no allocations allowed) ----------------
__device__ float4 g_p4_0[N0];
__device__ float4 g_p4_1[N1];
__device__ float4 g_p4_2[N2];
__device__ float4 g_p4_3[N3];
__device__ int    g_sel0[N1];
__device__ int    g_sel1[N2];
__device__ int    g_sel2[N3];
__device__ int    g_sori[N0];     // per-level sorted->original index scratch
__device__ float4 g_h0[N0 * 4];   // 16 floats per point
__device__ float4 g_x1[N1 * 4];
__device__ float4 g_x2[N2 * 4];
__device__ float4 g_x3[N3 * 4];
__device__ float4 g_f2[N2 * 4];
__device__ float4 g_f1[N1 * 4];
__device__ float4 g_f0[N0 * 4];

// ---------------- prep: pack pos + squared norm into float4 ----------------
__global__ void prep_kernel(const float* __restrict__ pos) {
    int i = blockIdx.x * blockDim.x + threadIdx.x;
    if (i >= N0) return;
    float x = pos[3 * i], y = pos[3 * i + 1], z = pos[3 * i + 2];
    float nb = __fadd_rn(__fadd_rn(__fmul_rn(x, x), __fmul_rn(y, y)), __fmul_rn(z, z));
    g_p4_0[i] = make_float4(x, y, z, nb);
}

// no-op kernel: shifts launch indices so the ncu capture slot lands on fps0
__global__ void warm_kernel() {}

__device__ __forceinline__ void load16(const float4* __restrict__ row, float* v) {
    float4 a = row[0], b = row[1], c = row[2], d = row[3];
    v[0] = a.x; v[1] = a.y; v[2] = a.z; v[3] = a.w;
    v[4] = b.x; v[5] = b.y; v[6] = b.z; v[7] = b.w;
    v[8] = c.x; v[9] = c.y; v[10] = c.z; v[11] = c.w;
    v[12] = d.x; v[13] = d.y; v[14] = d.z; v[15] = d.w;
}

__device__ __forceinline__ void store16(float4* __restrict__ row, const float* v) {
    row[0] = make_float4(v[0], v[1], v[2], v[3]);
    row[1] = make_float4(v[4], v[5], v[6], v[7]);
    row[2] = make_float4(v[8], v[9], v[10], v[11]);
    row[3] = make_float4(v[12], v[13], v[14], v[15]);
}

// ---------------- lin_in ----------------
__global__ void lin_in_kernel(const float* __restrict__ x,
                              const float* __restrict__ W0, const float* __restrict__ b0,
                              const float* __restrict__ W1, const float* __restrict__ b1) {
    __shared__ float sW0[256], sW1[256], sb0[16], sb1[16];
    int t = threadIdx.x;
    for (int i = t; i < 256; i += blockDim.x) { sW0[i] = W0[i]; sW1[i] = W1[i]; }
    if (t < 16) { sb0[t] = b0[t]; sb1[t] = b1[t]; }
    __syncthreads();
    int g = blockIdx.x * blockDim.x + t;
    if (g >= N0) return;
    float in[16], hid[16], out[16];
    load16((const float4*)(x + g * 16), in);
#pragma unroll
    for (int o = 0; o < 16; o++) hid[o] = sb0[o];
#pragma unroll
    for (int i = 0; i < 16; i++) {
        float v = in[i];
#pragma unroll
        for (int o = 0; o < 16; o++) hid[o] = fmaf(v, sW0[i * 16 + o], hid[o]);
    }
#pragma unroll
    for (int o = 0; o < 16; o++) hid[o] = fmaxf(hid[o], 0.0f);
#pragma unroll
    for (int o = 0; o < 16; o++) out[o] = sb1[o];
#pragma unroll
    for (int i = 0; i < 16; i++) {
        float v = hid[i];
#pragma unroll
        for (int o = 0; o < 16; o++) out[o] = fmaf(v, sW1[i * 16 + o], out[o]);
    }
#pragma unroll
    for (int o = 0; o < 16; o++) out[o] = fmaxf(out[o], 0.0f);
    store16(&g_h0[g * 4], out);
}

// ---------------- FPS with spatial sort + AABB pruning + leader reduce ----------------
template <int GB>
__device__ __forceinline__ int mcell(float x, float y, float z) {
    const float inv = (float)(1 << GB) * (1.0f / 32.0f);
    int cx = min((1 << GB) - 1, max(0, (int)(x * inv)));
    int cy = min((1 << GB) - 1, max(0, (int)(y * inv)));
    int cz = min((1 << GB) - 1, max(0, (int)(z * inv)));
    int m = 0;
#pragma unroll
    for (int b = 0; b < GB; b++)
        m |= (((cx >> b) & 1) << (3 * b)) | (((cy >> b) & 1) << (3 * b + 1)) |
             (((cz >> b) & 1) << (3 * b + 2));
    return m;
}

// NPTS points, select M, PTS = NPTS/1024 points per thread, GB grid bits per dim
template <int NPTS, int M, int PTS, int GB>
__global__ __launch_bounds__(FPS_T, 1)
void fps_kernel(const float4* __restrict__ p4, int* __restrict__ sel, int* __restrict__ sori) {
    constexpr int NCELL = 1 << (3 * GB);
    constexpr int LOGP = (PTS == 16) ? 4 : (PTS == 8) ? 3 : 2;
    __shared__ int s_hist[4096];
    __shared__ unsigned s_val[32];   // persistent per-warp best value (no parity)
    __shared__ int s_si[32];         // persistent per-warp best sorted-index
    __shared__ float4 s_ctrv;        // published center (x,y,z)
    __shared__ int s_misc[40];

    extern __shared__ float sm[];
    float* px = sm;
    float* py = sm + NPTS;
    float* pz = sm + 2 * NPTS;

    const int t = threadIdx.x;
    const int lane = t & 31;
    const int wid = t >> 5;

    // ---- phase 1: histogram ----
    for (int i = t; i < NCELL; i += FPS_T) s_hist[i] = 0;
    __syncthreads();
    for (int i = t; i < NPTS; i += FPS_T) {
        float4 p = p4[i];
        atomicAdd(&s_hist[mcell<GB>(p.x, p.y, p.z)], 1);
    }
    __syncthreads();

    // ---- phase 2: exclusive block scan of s_hist[0..NCELL) ----
    {
        constexpr int PER = (NCELL + FPS_T - 1) / FPS_T;
        int base = t * PER;
        int vals[PER];
        int run = 0;
#pragma unroll
        for (int q = 0; q < PER; q++) {
            int v = (base + q < NCELL) ? s_hist[base + q] : 0;
            vals[q] = v;
            run += v;
        }
        int inc = run;
#pragma unroll
        for (int off = 1; off < 32; off <<= 1) {
            int nb = __shfl_up_sync(0xffffffffu, inc, off);
            if (lane >= off) inc += nb;
        }
        if (lane == 31) s_misc[8 + wid] = inc;
        __syncthreads();
        if (t < 32) {
            int w = s_misc[8 + t];
            int winc = w;
#pragma unroll
            for (int off = 1; off < 32; off <<= 1) {
                int nb = __shfl_up_sync(0xffffffffu, winc, off);
                if (t >= off) winc += nb;
            }
            s_misc[8 + t] = winc - w;
        }
        __syncthreads();
        int off0 = s_misc[8 + wid] + (inc - run);
#pragma unroll
        for (int q = 0; q < PER; q++) {
            if (base + q < NCELL) s_hist[base + q] = off0;
            off0 += vals[q];
        }
    }
    __syncthreads();

    // ---- phase 3: scatter into transposed smem layout ----
    for (int i = t; i < NPTS; i += FPS_T) {
        float4 p = p4[i];
        int d = atomicAdd(&s_hist[mcell<GB>(p.x, p.y, p.z)], 1);
        int slot = (d & (PTS - 1)) * FPS_T + (d >> LOGP);
        px[slot] = p.x; py[slot] = p.y; pz[slot] = p.z;
        sori[d] = i;
        if (i == 0) s_misc[0] = d;
    }
    __syncthreads();

    // ---- phase 4: per-thread AABB + mind init ----
    float mind[PTS];
    float lox = CUDART_INF_F, loy = CUDART_INF_F, loz = CUDART_INF_F;
    float hix = -CUDART_INF_F, hiy = -CUDART_INF_F, hiz = -CUDART_INF_F;
#pragma unroll
    for (int k = 0; k < PTS; k++) {
        int slot = k * FPS_T + t;
        float X = px[slot], Y = py[slot], Z = pz[slot];
        lox = fminf(lox, X); hix = fmaxf(hix, X);
        loy = fminf(loy, Y); hiy = fmaxf(hiy, Y);
        loz = fminf(loz, Z); hiz = fmaxf(hiz, Z);
        mind[k] = CUDART_INF_F;
    }

    float chunk_val = CUDART_INF_F;
    int chunk_si = t * PTS;
    if (lane == 0) { s_val[wid] = __float_as_uint(CUDART_INF_F); s_si[wid] = chunk_si; }

    // prologue: publish the first center (original point 0)
    if (wid == 0) {
        int j0 = s_misc[0];
        int slotj = (j0 & (PTS - 1)) * FPS_T + (j0 >> LOGP);
        if (lane < 3) {
            float cv = (lane == 0) ? px[slotj] : (lane == 1) ? py[slotj] : pz[slotj];
            ((float*)&s_ctrv)[lane] = cv;
        }
        if (lane == 0) sel[0] = j0;
    }
    __syncthreads();

    // ---- phase 5: the FPS scan (leader-reduce, two light barriers) ----
    for (int step = 1; step < M; ++step) {
        float4 c = s_ctrv;   // one broadcast LDS.128 per warp

        float ax = fmaxf(fmaxf(lox - c.x, c.x - hix), 0.0f);
        float ay = fmaxf(fmaxf(loy - c.y, c.y - hiy), 0.0f);
        float az = fmaxf(fmaxf(loz - c.z, c.z - hiz), 0.0f);
        float lb = fmaf(ax, ax, fmaf(ay, ay, az * az)) * 0.9999f;
        bool touch = lb < chunk_val;

        if (__ballot_sync(0xffffffffu, touch)) {
            if (touch) {
#pragma unroll
                for (int k = 0; k < PTS; k++) {
                    int slot = k * FPS_T + t;
                    float dx = __fadd_rn(px[slot], -c.x);
                    float dy = __fadd_rn(py[slot], -c.y);
                    float dz = __fadd_rn(pz[slot], -c.z);
                    float d2 = __fadd_rn(__fadd_rn(__fmul_rn(dx, dx), __fmul_rn(dy, dy)),
                                         __fmul_rn(dz, dz));
                    mind[k] = fminf(mind[k], d2);
                }
                float red[PTS];
#pragma unroll
                for (int k = 0; k < PTS; k++) red[k] = mind[k];
#pragma unroll
                for (int w = PTS / 2; w >= 1; w >>= 1)
#pragma unroll
                    for (int k = 0; k < PTS / 2; k++)
                        if (k < w) red[k] = fmaxf(red[k], red[k + w]);
                float bv = red[0];
                unsigned msk = 0u;
#pragma unroll
                for (int k = 0; k < PTS; k++)
                    if (mind[k] == bv) msk |= (1u << k);
                chunk_val = bv;
                chunk_si = t * PTS + (__ffs(msk) - 1);
            }
            // warp reduce (only warps that had any touch): REDUX on positive-float bits
            unsigned mybits = __float_as_uint(chunk_val);
            unsigned wmax = __reduce_max_sync(0xffffffffu, mybits);
            unsigned who = __ballot_sync(0xffffffffu, mybits == wmax);
            int src = __ffs(who) - 1;
            int wsi = __shfl_sync(0xffffffffu, chunk_si, src);
            if (lane == 0) { s_val[wid] = wmax; s_si[wid] = wsi; }
        }
        __syncthreads();   // bar1: per-warp bests visible

        if (wid == 0) {
            // leader block reduce over the 32 persistent warp bests
            unsigned v = s_val[lane];
            unsigned bmax = __reduce_max_sync(0xffffffffu, v);
            unsigned wwin = __ballot_sync(0xffffffffu, v == bmax);
            int widwin = __ffs(wwin) - 1;
            int si = s_si[widwin];
            int slotj = (si & (PTS - 1)) * FPS_T + (si >> LOGP);
            if (lane < 3) {
                float cv = (lane == 0) ? px[slotj] : (lane == 1) ? py[slotj] : pz[slotj];
                ((float*)&s_ctrv)[lane] = cv;
            }
            if (lane == 0) sel[step] = si;
        }
        __syncthreads();   // bar2: new center visible
    }

    // ---- phase 6: remap raw sorted indices to original indices ----
    for (int i = t; i < M; i += FPS_T) {
        int si_ = sel[i];
        sel[i] = sori[si_];
    }
}

// ---------------- gather sampled positions ----------------
__global__ void gather_kernel(const float4* __restrict__ src, const int* __restrict__ sel,
                              float4* __restrict__ dst, int m) {
    int i = blockIdx.x * blockDim.x + threadIdx.x;
    if (i < m) dst[i] = src[sel[i]];
}

// ---------------- SA: radius group + PointConv + max-agg ----------------
template <int NSRC>
__global__ void sa_conv_kernel(const float4* __restrict__ p4s, const float4* __restrict__ p4t,
                               const float4* __restrict__ hs, float4* __restrict__ xt,
                               const float* __restrict__ W0, const float* __restrict__ b0,
                               const float* __restrict__ W1, const float* __restrict__ b1,
                               int ntgt) {
    __shared__ float sW0[19 * 19], sW1[19 * 16], sb0[19], sb1[16];
    int t = threadIdx.x;
    for (int i = t; i < 361; i += blockDim.x) sW0[i] = W0[i];
    for (int i = t; i < 304; i += blockDim.x) sW1[i] = W1[i];
    if (t < 19) sb0[t] = b0[t];
    if (t < 16) sb1[t] = b1[t];
    __syncthreads();

    int warp = (blockIdx.x * blockDim.x + t) >> 5;
    int lane = t & 31;
    if (warp >= ntgt) return;

    float4 pt = p4t[warp];
    float na = pt.w;
    float myd = 0.0f;
    int myj = 0;
    int cnt = 0;

    for (int base = 0; base < NSRC; base += 32) {
        int j = base + lane;
        float4 ps = p4s[j];
        float dot = fmaf(pt.x, ps.x, fmaf(pt.y, ps.y, pt.z * ps.z));
        float d2 = fmaxf((na + ps.w) - 2.0f * dot, 0.0f);
        bool hit = d2 <= R2C;
        unsigned mm = __ballot_sync(0xffffffffu, hit);
        while (mm) {
            int b = __ffs(mm) - 1;
            mm &= mm - 1;
            float nd = __shfl_sync(0xffffffffu, d2, b);
            int nj = base + b;
            if (cnt < 32) {
                if (lane == cnt) { myd = nd; myj = nj; }
                cnt++;
            } else {
                float mv = (lane < cnt) ? myd : -CUDART_INF_F;
                int ml = lane;
#pragma unroll
                for (int off = 16; off; off >>= 1) {
                    float ov = __shfl_xor_sync(0xffffffffu, mv, off);
                    int ol = __shfl_xor_sync(0xffffffffu, ml, off);
                    if (ov > mv) { mv = ov; ml = ol; }
                }
                if (nd < mv && lane == ml) { myd = nd; myj = nj; }
            }
        }
    }

    bool valid = lane < cnt;
    int jj = valid ? myj : 0;
    float in[19];
    load16(&hs[jj * 4], in);
    float4 sp = p4s[jj];
    in[16] = sp.x - pt.x;
    in[17] = sp.y - pt.y;
    in[18] = sp.z - pt.z;

    float hid[19];
#pragma unroll
    for (int o = 0; o < 19; o++) hid[o] = sb0[o];
#pragma unroll
    for (int i = 0; i < 19; i++) {
        float v = in[i];
#pragma unroll
        for (int o = 0; o < 19; o++) hid[o] = fmaf(v, sW0[i * 19 + o], hid[o]);
    }
#pragma unroll
    for (int o = 0; o < 19; o++) hid[o] = fmaxf(hid[o], 0.0f);

    float out[16];
#pragma unroll
    for (int o = 0; o < 16; o++) out[o] = sb1[o];
#pragma unroll
    for (int i = 0; i < 19; i++) {
        float v = hid[i];
#pragma unroll
        for (int o = 0; o < 16; o++) out[o] = fmaf(v, sW1[i * 16 + o], out[o]);
    }
    float res[16];
#pragma unroll
    for (int c = 0; c < 16; c++) {
        float r = valid ? fmaxf(out[c], 0.0f) : -CUDART_INF_F;
#pragma unroll
        for (int off = 16; off; off >>= 1) r = fmaxf(r, __shfl_xor_sync(0xffffffffu, r, off));
        res[c] = r;
    }
    if (lane == 0) store16(&xt[warp * 4], res);
}

// ---------------- FP: kNN(3) interpolate + MLP(32->32->16) ----------------
template <int NC>
__global__ void fp_kernel(const float4* __restrict__ p4f, const float4* __restrict__ p4c,
                          const float4* __restrict__ xc, const float4* __restrict__ xs,
                          float4* __restrict__ xf,
                          const float* __restrict__ W0, const float* __restrict__ b0,
                          const float* __restrict__ W1, const float* __restrict__ b1,
                          int nf) {
    __shared__ float sW0[32 * 32], sW1[32 * 16], sb0[32], sb1[16];
    int t = threadIdx.x;
    for (int i = t; i < 1024; i += blockDim.x) sW0[i] = W0[i];
    for (int i = t; i < 512; i += blockDim.x) sW1[i] = W1[i];
    if (t < 32) sb0[t] = b0[t];
    if (t < 16) sb1[t] = b1[t];
    __syncthreads();

    int g = blockIdx.x * blockDim.x + t;
    if (g >= nf) return;
    float4 f = p4f[g];
    float na = f.w;
    float d0 = CUDART_INF_F, d1 = CUDART_INF_F, d2 = CUDART_INF_F;
    int i0 = 0, i1 = 0, i2 = 0;
    for (int j = 0; j < NC; j++) {
        float4 c = p4c[j];
        float dot = fmaf(f.x, c.x, fmaf(f.y, c.y, f.z * c.z));
        float dd = fmaxf((na + c.w) - 2.0f * dot, 0.0f);
        if (dd < d0) {
            d2 = d1; i2 = i1; d1 = d0; i1 = i0; d0 = dd; i0 = j;
        } else if (dd < d1) {
            d2 = d1; i2 = i1; d1 = dd; i1 = j;
        } else if (dd < d2) {
            d2 = dd; i2 = j;
        }
    }
    float w0 = 1.0f / fmaxf(d0, 1e-16f);
    float w1 = 1.0f / fmaxf(d1, 1e-16f);
    float w2 = 1.0f / fmaxf(d2, 1e-16f);
    float ws = w0 + w1 + w2;
    w0 /= ws; w1 /= ws; w2 /= ws;

    float a0[16], a1[16], a2[16], in[32];
    load16(&xc[i0 * 4], a0);
    load16(&xc[i1 * 4], a1);
    load16(&xc[i2 * 4], a2);
#pragma unroll
    for (int c = 0; c < 16; c++) in[c] = (a0[c] * w0 + a1[c] * w1) + a2[c] * w2;
    load16(&xs[g * 4], in + 16);

    float hid[32];
#pragma unroll
    for (int o = 0; o < 32; o++) hid[o] = sb0[o];
#pragma unroll
    for (int i = 0; i < 32; i++) {
        float v = in[i];
#pragma unroll
        for (int o = 0; o < 32; o++) hid[o] = fmaf(v, sW0[i * 32 + o], hid[o]);
    }
#pragma unroll
    for (int o = 0; o < 32; o++) hid[o] = fmaxf(hid[o], 0.0f);
    float out[16];
#pragma unroll
    for (int o = 0; o < 16; o++) out[o] = sb1[o];
#pragma unroll
    for (int i = 0; i < 32; i++) {
        float v = hid[i];
#pragma unroll
        for (int o = 0; o < 16; o++) out[o] = fmaf(v, sW1[i * 16 + o], out[o]);
    }
#pragma unroll
    for (int o = 0; o < 16; o++) out[o] = fmaxf(out[o], 0.0f);
    store16(&xf[g * 4], out);
}

// ---------------- lin_out ----------------
__global__ void lin_out_kernel(const float* __restrict__ W0, const float* __restrict__ b0,
                               const float* __restrict__ W1, const float* __restrict__ b1,
                               float* __restrict__ out) {
    __shared__ float sW0[256], sW1[32], sb0[16], sb1[2];
    int t = threadIdx.x;
    for (int i = t; i < 256; i += blockDim.x) sW0[i] = W0[i];
    if (t < 32) sW1[t] = W1[t];
    if (t < 16) sb0[t] = b0[t];
    if (t < 2) sb1[t] = b1[t];
    __syncthreads();
    int g = blockIdx.x * blockDim.x + t;
    if (g >= N0) return;
    float in[16], hid[16];
    load16(&g_f0[g * 4], in);
#pragma unroll
    for (int o = 0; o < 16; o++) hid[o] = sb0[o];
#pragma unroll
    for (int i = 0; i < 16; i++) {
        float v = in[i];
#pragma unroll
        for (int o = 0; o < 16; o++) hid[o] = fmaf(v, sW0[i * 16 + o], hid[o]);
    }
    float o0 = sb1[0], o1 = sb1[1];
#pragma unroll
    for (int i = 0; i < 16; i++) {
        float v = fmaxf(hid[i], 0.0f);
        o0 = fmaf(v, sW1[i * 2 + 0], o0);
        o1 = fmaf(v, sW1[i * 2 + 1], o1);
    }
    out[g * 2 + 0] = o0;
    out[g * 2 + 1] = o1;
}

// ---------------- host launcher ----------------
extern "C" void kernel_launch(void* const* d_in, const int* in_sizes, int n_in,
                              void* d_out, int out_size) {
    const float* x = (const float*)d_in[0];
    const float* pos = (const float*)d_in[1];
    const float* liW0 = (const float*)d_in[3];
    const float* lib0 = (const float*)d_in[4];
    const float* liW1 = (const float*)d_in[5];
    const float* lib1 = (const float*)d_in[6];
    const float* saW0 = (const float*)d_in[7];
    const float* sab0 = (const float*)d_in[8];
    const float* saW1 = (const float*)d_in[9];
    const float* sab1 = (const float*)d_in[10];
    const float* fpW0 = (const float*)d_in[11];
    const float* fpb0 = (const float*)d_in[12];
    const float* fpW1 = (const float*)d_in[13];
    const float* fpb1 = (const float*)d_in[14];
    const float* loW0 = (const float*)d_in[15];
    const float* lob0 = (const float*)d_in[16];
    const float* loW1 = (const float*)d_in[17];
    const float* lob1 = (const float*)d_in[18];
    float* out = (float*)d_out;

    void *p40, *p41, *p42, *p43, *s0, *s1, *s2, *sori, *h0, *x1, *x2, *x3, *f2, *f1, *f0;
    cudaGetSymbolAddress(&p40, g_p4_0);
    cudaGetSymbolAddress(&p41, g_p4_1);
    cudaGetSymbolAddress(&p42, g_p4_2);
    cudaGetSymbolAddress(&p43, g_p4_3);
    cudaGetSymbolAddress(&s0, g_sel0);
    cudaGetSymbolAddress(&s1, g_sel1);
    cudaGetSymbolAddress(&s2, g_sel2);
    cudaGetSymbolAddress(&sori, g_sori);
    cudaGetSymbolAddress(&h0, g_h0);
    cudaGetSymbolAddress(&x1, g_x1);
    cudaGetSymbolAddress(&x2, g_x2);
    cudaGetSymbolAddress(&x3, g_x3);
    cudaGetSymbolAddress(&f2, g_f2);
    cudaGetSymbolAddress(&f1, g_f1);
    cudaGetSymbolAddress(&f0, g_f0);

    size_t sm0 = (size_t)N0 * 12;
    size_t sm1 = (size_t)N1 * 12;
    size_t sm2 = (size_t)N2 * 12;
    cudaFuncSetAttribute((const void*)fps_kernel<N0, N1, 16, 4>,
                         cudaFuncAttributeMaxDynamicSharedMemorySize, (int)sm0);
    cudaFuncSetAttribute((const void*)fps_kernel<N1, N2, 8, 3>,
                         cudaFuncAttributeMaxDynamicSharedMemorySize, (int)sm1);
    cudaFuncSetAttribute((const void*)fps_kernel<N2, N3, 4, 3>,
                         cudaFuncAttributeMaxDynamicSharedMemorySize, (int)sm2);

    prep_kernel<<<(N0 + 255) / 256, 256>>>(pos);
    warm_kernel<<<1, 32>>>();
    lin_in_kernel<<<N0 / 128, 128>>>(x, liW0, lib0, liW1, lib1);

    // level 0
    fps_kernel<N0, N1, 16, 4><<<1, FPS_T, sm0>>>((const float4*)p40, (int*)s0, (int*)sori);
    gather_kernel<<<N1 / 256, 256>>>((const float4*)p40, (const int*)s0, (float4*)p41, N1);
    sa_conv_kernel<N0><<<N1 * 32 / 256, 256>>>((const float4*)p40, (const float4*)p41,
                                               (const float4*)h0, (float4*)x1,
                                               saW0, sab0, saW1, sab1, N1);
    // level 1
    fps_kernel<N1, N2, 8, 3><<<1, FPS_T, sm1>>>((const float4*)p41, (int*)s1, (int*)sori);
    gather_kernel<<<N2 / 256, 256>>>((const float4*)p41, (const int*)s1, (float4*)p42, N2);
    sa_conv_kernel<N1><<<N2 * 32 / 256, 256>>>((const float4*)p41, (const float4*)p42,
                                               (const float4*)x1, (float4*)x2,
                                               saW0 + 361, sab0 + 19, saW1 + 304, sab1 + 16, N2);
    // level 2
    fps_kernel<N2, N3, 4, 3><<<1, FPS_T, sm2>>>((const float4*)p42, (int*)s2, (int*)sori);
    gather_kernel<<<N3 / 256, 256>>>((const float4*)p42, (const int*)s2, (float4*)p43, N3);
    sa_conv_kernel<N2><<<N3 * 32 / 256, 256>>>((const float4*)p42, (const float4*)p43,
                                               (const float4*)x2, (float4*)x3,
                                               saW0 + 722, sab0 + 38, saW1 + 608, sab1 + 32, N3);

    // FP path (coarse -> fine)
    fp_kernel<N3><<<N2 / 128, 128>>>((const float4*)p42, (const float4*)p43,
                                     (const float4*)x3, (const float4*)x2, (float4*)f2,
                                     fpW0 + 2 * 1024, fpb0 + 2 * 32, fpW1 + 2 * 512, fpb1 + 2 * 16,
                                     N2);
    fp_kernel<N2><<<N1 / 128, 128>>>((const float4*)p41, (const float4*)p42,
                                     (const float4*)f2, (const float4*)x1, (float4*)f1,
                                     fpW0 + 1024, fpb0 + 32, fpW1 + 512, fpb1 + 16, N1);
    fp_kernel<N1><<<N0 / 128, 128>>>((const float4*)p40, (const float4*)p41,
                                     (const float4*)f1, (const float4*)h0, (float4*)f0,
                                     fpW0, fpb0, fpW1, fpb1, N0);

    lin_out_kernel<<<N0 / 256, 256>>>(loW0, lob0, loW1, lob1, out);
}

// round 10
// speedup vs baseline: 2.3076x; 1.0491x over previous
#include <cuda_runtime.h>
#include <math_constants.h>

#define N0 16384
#define N1 8192
#define N2 4096
#define N3 2048
#define R2C 4.0f
#define FPS_T 1024

// ---------------- device scratch (no allocations allowed) ----------------
__device__ float4 g_p4_0[N0];
__device__ float4 g_p4_1[N1];
__device__ float4 g_p4_2[N2];
__device__ float4 g_p4_3[N3];
__device__ int    g_sel0[N1];
__device__ int    g_sel1[N2];
__device__ int    g_sel2[N3];
__device__ int    g_sori[N0];     // per-level sorted->original index scratch
__device__ float4 g_h0[N0 * 4];   // 16 floats per point
__device__ float4 g_x1[N1 * 4];
__device__ float4 g_x2[N2 * 4];
__device__ float4 g_x3[N3 * 4];
__device__ float4 g_f2[N2 * 4];
__device__ float4 g_f1[N1 * 4];
__device__ float4 g_f0[N0 * 4];

// ---------------- packed f32x2 helpers (component-wise IEEE rn, identical to scalar) ----
__device__ __forceinline__ unsigned long long pk2(float lo, float hi) {
    unsigned long long r;
    asm("mov.b64 %0, {%1, %2};" : "=l"(r) : "f"(lo), "f"(hi));
    return r;
}
__device__ __forceinline__ void unpk2(unsigned long long v, float& lo, float& hi) {
    asm("mov.b64 {%0, %1}, %2;" : "=f"(lo), "=f"(hi) : "l"(v));
}
__device__ __forceinline__ unsigned long long add2(unsigned long long a, unsigned long long b) {
    unsigned long long r;
    asm("add.rn.f32x2 %0, %1, %2;" : "=l"(r) : "l"(a), "l"(b));
    return r;
}
__device__ __forceinline__ unsigned long long mul2(unsigned long long a, unsigned long long b) {
    unsigned long long r;
    asm("mul.rn.f32x2 %0, %1, %2;" : "=l"(r) : "l"(a), "l"(b));
    return r;
}

// ---------------- prep: pack pos + squared norm into float4 ----------------
__global__ void prep_kernel(const float* __restrict__ pos) {
    int i = blockIdx.x * blockDim.x + threadIdx.x;
    if (i >= N0) return;
    float x = pos[3 * i], y = pos[3 * i + 1], z = pos[3 * i + 2];
    float nb = __fadd_rn(__fadd_rn(__fmul_rn(x, x), __fmul_rn(y, y)), __fmul_rn(z, z));
    g_p4_0[i] = make_float4(x, y, z, nb);
}

// no-op kernel: shifts launch indices so the ncu capture slot lands on fps0
__global__ void warm_kernel() {}

__device__ __forceinline__ void load16(const float4* __restrict__ row, float* v) {
    float4 a = row[0], b = row[1], c = row[2], d = row[3];
    v[0] = a.x; v[1] = a.y; v[2] = a.z; v[3] = a.w;
    v[4] = b.x; v[5] = b.y; v[6] = b.z; v[7] = b.w;
    v[8] = c.x; v[9] = c.y; v[10] = c.z; v[11] = c.w;
    v[12] = d.x; v[13] = d.y; v[14] = d.z; v[15] = d.w;
}

__device__ __forceinline__ void store16(float4* __restrict__ row, const float* v) {
    row[0] = make_float4(v[0], v[1], v[2], v[3]);
    row[1] = make_float4(v[4], v[5], v[6], v[7]);
    row[2] = make_float4(v[8], v[9], v[10], v[11]);
    row[3] = make_float4(v[12], v[13], v[14], v[15]);
}

// ---------------- lin_in ----------------
__global__ void lin_in_kernel(const float* __restrict__ x,
                              const float* __restrict__ W0, const float* __restrict__ b0,
                              const float* __restrict__ W1, const float* __restrict__ b1) {
    __shared__ float sW0[256], sW1[256], sb0[16], sb1[16];
    int t = threadIdx.x;
    for (int i = t; i < 256; i += blockDim.x) { sW0[i] = W0[i]; sW1[i] = W1[i]; }
    if (t < 16) { sb0[t] = b0[t]; sb1[t] = b1[t]; }
    __syncthreads();
    int g = blockIdx.x * blockDim.x + t;
    if (g >= N0) return;
    float in[16], hid[16], out[16];
    load16((const float4*)(x + g * 16), in);
#pragma unroll
    for (int o = 0; o < 16; o++) hid[o] = sb0[o];
#pragma unroll
    for (int i = 0; i < 16; i++) {
        float v = in[i];
#pragma unroll
        for (int o = 0; o < 16; o++) hid[o] = fmaf(v, sW0[i * 16 + o], hid[o]);
    }
#pragma unroll
    for (int o = 0; o < 16; o++) hid[o] = fmaxf(hid[o], 0.0f);
#pragma unroll
    for (int o = 0; o < 16; o++) out[o] = sb1[o];
#pragma unroll
    for (int i = 0; i < 16; i++) {
        float v = hid[i];
#pragma unroll
        for (int o = 0; o < 16; o++) out[o] = fmaf(v, sW1[i * 16 + o], out[o]);
    }
#pragma unroll
    for (int o = 0; o < 16; o++) out[o] = fmaxf(out[o], 0.0f);
    store16(&g_h0[g * 4], out);
}

// ---------------- FPS: spatial sort + warp-AABB pruning + packed scan + leader reduce ----
template <int GB>
__device__ __forceinline__ int mcell(float x, float y, float z) {
    const float inv = (float)(1 << GB) * (1.0f / 32.0f);
    int cx = min((1 << GB) - 1, max(0, (int)(x * inv)));
    int cy = min((1 << GB) - 1, max(0, (int)(y * inv)));
    int cz = min((1 << GB) - 1, max(0, (int)(z * inv)));
    int m = 0;
#pragma unroll
    for (int b = 0; b < GB; b++)
        m |= (((cx >> b) & 1) << (3 * b)) | (((cy >> b) & 1) << (3 * b + 1)) |
             (((cz >> b) & 1) << (3 * b + 2));
    return m;
}

// pair-interleaved float index for sorted point (thread tt, chunk slot kk)
template <int LOGP>
__device__ __forceinline__ int pair_fidx(int tt, int kk) {
    return (kk >> 1) * (2 * FPS_T) + 2 * tt + (kk & 1);
}

// NPTS points, select M, PTS = NPTS/1024 points per thread, GB grid bits per dim
template <int NPTS, int M, int PTS, int GB>
__global__ __launch_bounds__(FPS_T, 1)
void fps_kernel(const float4* __restrict__ p4, int* __restrict__ sel, int* __restrict__ sori) {
    constexpr int NCELL = 1 << (3 * GB);
    constexpr int LOGP = (PTS == 16) ? 4 : (PTS == 8) ? 3 : 2;
    __shared__ int s_hist[4096];
    __shared__ unsigned s_val[32];   // persistent per-warp best value
    __shared__ int s_si[32];         // persistent per-warp best sorted-index
    __shared__ float4 s_ctrv;        // published center (x,y,z)
    __shared__ int s_misc[40];

    extern __shared__ float sm[];
    float* px = sm;
    float* py = sm + NPTS;
    float* pz = sm + 2 * NPTS;

    const int t = threadIdx.x;
    const int lane = t & 31;
    const int wid = t >> 5;

    // ---- phase 1: histogram ----
    for (int i = t; i < NCELL; i += FPS_T) s_hist[i] = 0;
    __syncthreads();
    for (int i = t; i < NPTS; i += FPS_T) {
        float4 p = p4[i];
        atomicAdd(&s_hist[mcell<GB>(p.x, p.y, p.z)], 1);
    }
    __syncthreads();

    // ---- phase 2: exclusive block scan of s_hist[0..NCELL) ----
    {
        constexpr int PER = (NCELL + FPS_T - 1) / FPS_T;
        int base = t * PER;
        int vals[PER];
        int run = 0;
#pragma unroll
        for (int q = 0; q < PER; q++) {
            int v = (base + q < NCELL) ? s_hist[base + q] : 0;
            vals[q] = v;
            run += v;
        }
        int inc = run;
#pragma unroll
        for (int off = 1; off < 32; off <<= 1) {
            int nb = __shfl_up_sync(0xffffffffu, inc, off);
            if (lane >= off) inc += nb;
        }
        if (lane == 31) s_misc[8 + wid] = inc;
        __syncthreads();
        if (t < 32) {
            int w = s_misc[8 + t];
            int winc = w;
#pragma unroll
            for (int off = 1; off < 32; off <<= 1) {
                int nb = __shfl_up_sync(0xffffffffu, winc, off);
                if (t >= off) winc += nb;
            }
            s_misc[8 + t] = winc - w;
        }
        __syncthreads();
        int off0 = s_misc[8 + wid] + (inc - run);
#pragma unroll
        for (int q = 0; q < PER; q++) {
            if (base + q < NCELL) s_hist[base + q] = off0;
            off0 += vals[q];
        }
    }
    __syncthreads();

    // ---- phase 3: scatter into pair-interleaved smem layout ----
    for (int i = t; i < NPTS; i += FPS_T) {
        float4 p = p4[i];
        int d = atomicAdd(&s_hist[mcell<GB>(p.x, p.y, p.z)], 1);
        int tt = d >> LOGP;
        int kk = d & (PTS - 1);
        int fidx = pair_fidx<LOGP>(tt, kk);
        px[fidx] = p.x; py[fidx] = p.y; pz[fidx] = p.z;
        sori[d] = i;
        if (i == 0) s_misc[0] = d;
    }
    __syncthreads();

    // ---- phase 4: per-thread mind init + WARP-level AABB ----
    float mind[PTS];
    float lox = CUDART_INF_F, loy = CUDART_INF_F, loz = CUDART_INF_F;
    float hix = -CUDART_INF_F, hiy = -CUDART_INF_F, hiz = -CUDART_INF_F;
#pragma unroll
    for (int k = 0; k < PTS; k++) {
        int fidx = pair_fidx<LOGP>(t, k);
        float X = px[fidx], Y = py[fidx], Z = pz[fidx];
        lox = fminf(lox, X); hix = fmaxf(hix, X);
        loy = fminf(loy, Y); hiy = fmaxf(hiy, Y);
        loz = fminf(loz, Z); hiz = fmaxf(hiz, Z);
        mind[k] = CUDART_INF_F;
    }
    // reduce lane AABBs to a warp AABB (uniform across lanes)
#pragma unroll
    for (int off = 16; off; off >>= 1) {
        lox = fminf(lox, __shfl_xor_sync(0xffffffffu, lox, off));
        hix = fmaxf(hix, __shfl_xor_sync(0xffffffffu, hix, off));
        loy = fminf(loy, __shfl_xor_sync(0xffffffffu, loy, off));
        hiy = fmaxf(hiy, __shfl_xor_sync(0xffffffffu, hiy, off));
        loz = fminf(loz, __shfl_xor_sync(0xffffffffu, loz, off));
        hiz = fmaxf(hiz, __shfl_xor_sync(0xffffffffu, hiz, off));
    }

    float wbest = CUDART_INF_F;   // warp-uniform cached best (REDUX result)
    if (lane == 0) { s_val[wid] = __float_as_uint(CUDART_INF_F); s_si[wid] = wid * 32 * PTS; }

    // prologue: publish the first center (original point 0)
    if (wid == 0) {
        int j0 = s_misc[0];
        int fidx = pair_fidx<LOGP>(j0 >> LOGP, j0 & (PTS - 1));
        if (lane < 3) {
            float cv = (lane == 0) ? px[fidx] : (lane == 1) ? py[fidx] : pz[fidx];
            ((float*)&s_ctrv)[lane] = cv;
        }
        if (lane == 0) sel[0] = j0;
    }
    __syncthreads();

    // ---- phase 5: the FPS scan ----
    for (int step = 1; step < M; ++step) {
        float4 c = s_ctrv;   // one broadcast LDS.128 per warp

        // warp-uniform AABB lower bound vs warp cached best: scalar branch, no ballot
        float ax = fmaxf(fmaxf(lox - c.x, c.x - hix), 0.0f);
        float ay = fmaxf(fmaxf(loy - c.y, c.y - hiy), 0.0f);
        float az = fmaxf(fmaxf(loz - c.z, c.z - hiz), 0.0f);
        float lb = fmaf(ax, ax, fmaf(ay, ay, az * az)) * 0.9999f;

        if (lb < wbest) {
            unsigned long long ncx2 = pk2(-c.x, -c.x);
            unsigned long long ncy2 = pk2(-c.y, -c.y);
            unsigned long long ncz2 = pk2(-c.z, -c.z);
            float bv = -CUDART_INF_F;
#pragma unroll
            for (int k2 = 0; k2 < PTS / 2; k2++) {
                int base = k2 * (2 * FPS_T) + 2 * t;
                unsigned long long X = *(const unsigned long long*)(px + base);
                unsigned long long Y = *(const unsigned long long*)(py + base);
                unsigned long long Z = *(const unsigned long long*)(pz + base);
                unsigned long long dX = add2(X, ncx2);
                unsigned long long dY = add2(Y, ncy2);
                unsigned long long dZ = add2(Z, ncz2);
                unsigned long long s2 = add2(add2(mul2(dX, dX), mul2(dY, dY)), mul2(dZ, dZ));
                float d2a, d2b;
                unpk2(s2, d2a, d2b);
                float mna = fminf(mind[2 * k2], d2a);
                mind[2 * k2] = mna;
                float mnb = fminf(mind[2 * k2 + 1], d2b);
                mind[2 * k2 + 1] = mnb;
                bv = fmaxf(bv, fmaxf(mna, mnb));
            }
            unsigned msk = 0u;
#pragma unroll
            for (int k = 0; k < PTS; k++)
                if (mind[k] == bv) msk |= (1u << k);
            int csi = t * PTS + (__ffs(msk) - 1);

            unsigned mybits = __float_as_uint(bv);
            unsigned wmax = __reduce_max_sync(0xffffffffu, mybits);
            unsigned who = __ballot_sync(0xffffffffu, mybits == wmax);
            int src = __ffs(who) - 1;
            int wsi = __shfl_sync(0xffffffffu, csi, src);
            wbest = __uint_as_float(wmax);
            if (lane == 0) { s_val[wid] = wmax; s_si[wid] = wsi; }
        }
        __syncthreads();   // bar1: per-warp bests visible

        if (wid == 0) {
            unsigned v = s_val[lane];
            unsigned bmax = __reduce_max_sync(0xffffffffu, v);
            unsigned wwin = __ballot_sync(0xffffffffu, v == bmax);
            int widwin = __ffs(wwin) - 1;
            int si = s_si[widwin];
            int fidx = pair_fidx<LOGP>(si >> LOGP, si & (PTS - 1));
            if (lane < 3) {
                float cv = (lane == 0) ? px[fidx] : (lane == 1) ? py[fidx] : pz[fidx];
                ((float*)&s_ctrv)[lane] = cv;
            }
            if (lane == 0) sel[step] = si;
        }
        __syncthreads();   // bar2: new center visible
    }

    // ---- phase 6: remap raw sorted indices to original indices ----
    for (int i = t; i < M; i += FPS_T) {
        int si_ = sel[i];
        sel[i] = sori[si_];
    }
}

// ---------------- gather sampled positions ----------------
__global__ void gather_kernel(const float4* __restrict__ src, const int* __restrict__ sel,
                              float4* __restrict__ dst, int m) {
    int i = blockIdx.x * blockDim.x + threadIdx.x;
    if (i < m) dst[i] = src[sel[i]];
}

// ---------------- SA: radius group + PointConv + max-agg ----------------
template <int NSRC>
__global__ void sa_conv_kernel(const float4* __restrict__ p4s, const float4* __restrict__ p4t,
                               const float4* __restrict__ hs, float4* __restrict__ xt,
                               const float* __restrict__ W0, const float* __restrict__ b0,
                               const float* __restrict__ W1, const float* __restrict__ b1,
                               int ntgt) {
    __shared__ float sW0[19 * 19], sW1[19 * 16], sb0[19], sb1[16];
    int t = threadIdx.x;
    for (int i = t; i < 361; i += blockDim.x) sW0[i] = W0[i];
    for (int i = t; i < 304; i += blockDim.x) sW1[i] = W1[i];
    if (t < 19) sb0[t] = b0[t];
    if (t < 16) sb1[t] = b1[t];
    __syncthreads();

    int warp = (blockIdx.x * blockDim.x + t) >> 5;
    int lane = t & 31;
    if (warp >= ntgt) return;

    float4 pt = p4t[warp];
    float na = pt.w;
    float myd = 0.0f;
    int myj = 0;
    int cnt = 0;

    for (int base = 0; base < NSRC; base += 32) {
        int j = base + lane;
        float4 ps = p4s[j];
        float dot = fmaf(pt.x, ps.x, fmaf(pt.y, ps.y, pt.z * ps.z));
        float d2 = fmaxf((na + ps.w) - 2.0f * dot, 0.0f);
        bool hit = d2 <= R2C;
        unsigned mm = __ballot_sync(0xffffffffu, hit);
        while (mm) {
            int b = __ffs(mm) - 1;
            mm &= mm - 1;
            float nd = __shfl_sync(0xffffffffu, d2, b);
            int nj = base + b;
            if (cnt < 32) {
                if (lane == cnt) { myd = nd; myj = nj; }
                cnt++;
            } else {
                float mv = (lane < cnt) ? myd : -CUDART_INF_F;
                int ml = lane;
#pragma unroll
                for (int off = 16; off; off >>= 1) {
                    float ov = __shfl_xor_sync(0xffffffffu, mv, off);
                    int ol = __shfl_xor_sync(0xffffffffu, ml, off);
                    if (ov > mv) { mv = ov; ml = ol; }
                }
                if (nd < mv && lane == ml) { myd = nd; myj = nj; }
            }
        }
    }

    bool valid = lane < cnt;
    int jj = valid ? myj : 0;
    float in[19];
    load16(&hs[jj * 4], in);
    float4 sp = p4s[jj];
    in[16] = sp.x - pt.x;
    in[17] = sp.y - pt.y;
    in[18] = sp.z - pt.z;

    float hid[19];
#pragma unroll
    for (int o = 0; o < 19; o++) hid[o] = sb0[o];
#pragma unroll
    for (int i = 0; i < 19; i++) {
        float v = in[i];
#pragma unroll
        for (int o = 0; o < 19; o++) hid[o] = fmaf(v, sW0[i * 19 + o], hid[o]);
    }
#pragma unroll
    for (int o = 0; o < 19; o++) hid[o] = fmaxf(hid[o], 0.0f);

    float out[16];
#pragma unroll
    for (int o = 0; o < 16; o++) out[o] = sb1[o];
#pragma unroll
    for (int i = 0; i < 19; i++) {
        float v = hid[i];
#pragma unroll
        for (int o = 0; o < 16; o++) out[o] = fmaf(v, sW1[i * 16 + o], out[o]);
    }
    float res[16];
#pragma unroll
    for (int c = 0; c < 16; c++) {
        float r = valid ? fmaxf(out[c], 0.0f) : -CUDART_INF_F;
#pragma unroll
        for (int off = 16; off; off >>= 1) r = fmaxf(r, __shfl_xor_sync(0xffffffffu, r, off));
        res[c] = r;
    }
    if (lane == 0) store16(&xt[warp * 4], res);
}

// ---------------- FP: kNN(3) interpolate + MLP(32->32->16) ----------------
template <int NC>
__global__ void fp_kernel(const float4* __restrict__ p4f, const float4* __restrict__ p4c,
                          const float4* __restrict__ xc, const float4* __restrict__ xs,
                          float4* __restrict__ xf,
                          const float* __restrict__ W0, const float* __restrict__ b0,
                          const float* __restrict__ W1, const float* __restrict__ b1,
                          int nf) {
    __shared__ float sW0[32 * 32], sW1[32 * 16], sb0[32], sb1[16];
    int t = threadIdx.x;
    for (int i = t; i < 1024; i += blockDim.x) sW0[i] = W0[i];
    for (int i = t; i < 512; i += blockDim.x) sW1[i] = W1[i];
    if (t < 32) sb0[t] = b0[t];
    if (t < 16) sb1[t] = b1[t];
    __syncthreads();

    int g = blockIdx.x * blockDim.x + t;
    if (g >= nf) return;
    float4 f = p4f[g];
    float na = f.w;
    float d0 = CUDART_INF_F, d1 = CUDART_INF_F, d2 = CUDART_INF_F;
    int i0 = 0, i1 = 0, i2 = 0;
    for (int j = 0; j < NC; j++) {
        float4 c = p4c[j];
        float dot = fmaf(f.x, c.x, fmaf(f.y, c.y, f.z * c.z));
        float dd = fmaxf((na + c.w) - 2.0f * dot, 0.0f);
        if (dd < d0) {
            d2 = d1; i2 = i1; d1 = d0; i1 = i0; d0 = dd; i0 = j;
        } else if (dd < d1) {
            d2 = d1; i2 = i1; d1 = dd; i1 = j;
        } else if (dd < d2) {
            d2 = dd; i2 = j;
        }
    }
    float w0 = 1.0f / fmaxf(d0, 1e-16f);
    float w1 = 1.0f / fmaxf(d1, 1e-16f);
    float w2 = 1.0f / fmaxf(d2, 1e-16f);
    float ws = w0 + w1 + w2;
    w0 /= ws; w1 /= ws; w2 /= ws;

    float a0[16], a1[16], a2[16], in[32];
    load16(&xc[i0 * 4], a0);
    load16(&xc[i1 * 4], a1);
    load16(&xc[i2 * 4], a2);
#pragma unroll
    for (int c = 0; c < 16; c++) in[c] = (a0[c] * w0 + a1[c] * w1) + a2[c] * w2;
    load16(&xs[g * 4], in + 16);

    float hid[32];
#pragma unroll
    for (int o = 0; o < 32; o++) hid[o] = sb0[o];
#pragma unroll
    for (int i = 0; i < 32; i++) {
        float v = in[i];
#pragma unroll
        for (int o = 0; o < 32; o++) hid[o] = fmaf(v, sW0[i * 32 + o], hid[o]);
    }
#pragma unroll
    for (int o = 0; o < 32; o++) hid[o] = fmaxf(hid[o], 0.0f);
    float out[16];
#pragma unroll
    for (int o = 0; o < 16; o++) out[o] = sb1[o];
#pragma unroll
    for (int i = 0; i < 32; i++) {
        float v = hid[i];
#pragma unroll
        for (int o = 0; o < 16; o++) out[o] = fmaf(v, sW1[i * 16 + o], out[o]);
    }
#pragma unroll
    for (int o = 0; o < 16; o++) out[o] = fmaxf(out[o], 0.0f);
    store16(&xf[g * 4], out);
}

// ---------------- lin_out ----------------
__global__ void lin_out_kernel(const float* __restrict__ W0, const float* __restrict__ b0,
                               const float* __restrict__ W1, const float* __restrict__ b1,
                               float* __restrict__ out) {
    __shared__ float sW0[256], sW1[32], sb0[16], sb1[2];
    int t = threadIdx.x;
    for (int i = t; i < 256; i += blockDim.x) sW0[i] = W0[i];
    if (t < 32) sW1[t] = W1[t];
    if (t < 16) sb0[t] = b0[t];
    if (t < 2) sb1[t] = b1[t];
    __syncthreads();
    int g = blockIdx.x * blockDim.x + t;
    if (g >= N0) return;
    float in[16], hid[16];
    load16(&g_f0[g * 4], in);
#pragma unroll
    for (int o = 0; o < 16; o++) hid[o] = sb0[o];
#pragma unroll
    for (int i = 0; i < 16; i++) {
        float v = in[i];
#pragma unroll
        for (int o = 0; o < 16; o++) hid[o] = fmaf(v, sW0[i * 16 + o], hid[o]);
    }
    float o0 = sb1[0], o1 = sb1[1];
#pragma unroll
    for (int i = 0; i < 16; i++) {
        float v = fmaxf(hid[i], 0.0f);
        o0 = fmaf(v, sW1[i * 2 + 0], o0);
        o1 = fmaf(v, sW1[i * 2 + 1], o1);
    }
    out[g * 2 + 0] = o0;
    out[g * 2 + 1] = o1;
}

// ---------------- host launcher ----------------
extern "C" void kernel_launch(void* const* d_in, const int* in_sizes, int n_in,
                              void* d_out, int out_size) {
    const float* x = (const float*)d_in[0];
    const float* pos = (const float*)d_in[1];
    const float* liW0 = (const float*)d_in[3];
    const float* lib0 = (const float*)d_in[4];
    const float* liW1 = (const float*)d_in[5];
    const float* lib1 = (const float*)d_in[6];
    const float* saW0 = (const float*)d_in[7];
    const float* sab0 = (const float*)d_in[8];
    const float* saW1 = (const float*)d_in[9];
    const float* sab1 = (const float*)d_in[10];
    const float* fpW0 = (const float*)d_in[11];
    const float* fpb0 = (const float*)d_in[12];
    const float* fpW1 = (const float*)d_in[13];
    const float* fpb1 = (const float*)d_in[14];
    const float* loW0 = (const float*)d_in[15];
    const float* lob0 = (const float*)d_in[16];
    const float* loW1 = (const float*)d_in[17];
    const float* lob1 = (const float*)d_in[18];
    float* out = (float*)d_out;

    void *p40, *p41, *p42, *p43, *s0, *s1, *s2, *sori, *h0, *x1, *x2, *x3, *f2, *f1, *f0;
    cudaGetSymbolAddress(&p40, g_p4_0);
    cudaGetSymbolAddress(&p41, g_p4_1);
    cudaGetSymbolAddress(&p42, g_p4_2);
    cudaGetSymbolAddress(&p43, g_p4_3);
    cudaGetSymbolAddress(&s0, g_sel0);
    cudaGetSymbolAddress(&s1, g_sel1);
    cudaGetSymbolAddress(&s2, g_sel2);
    cudaGetSymbolAddress(&sori, g_sori);
    cudaGetSymbolAddress(&h0, g_h0);
    cudaGetSymbolAddress(&x1, g_x1);
    cudaGetSymbolAddress(&x2, g_x2);
    cudaGetSymbolAddress(&x3, g_x3);
    cudaGetSymbolAddress(&f2, g_f2);
    cudaGetSymbolAddress(&f1, g_f1);
    cudaGetSymbolAddress(&f0, g_f0);

    size_t sm0 = (size_t)N0 * 12;
    size_t sm1 = (size_t)N1 * 12;
    size_t sm2 = (size_t)N2 * 12;
    cudaFuncSetAttribute((const void*)fps_kernel<N0, N1, 16, 4>,
                         cudaFuncAttributeMaxDynamicSharedMemorySize, (int)sm0);
    cudaFuncSetAttribute((const void*)fps_kernel<N1, N2, 8, 3>,
                         cudaFuncAttributeMaxDynamicSharedMemorySize, (int)sm1);
    cudaFuncSetAttribute((const void*)fps_kernel<N2, N3, 4, 3>,
                         cudaFuncAttributeMaxDynamicSharedMemorySize, (int)sm2);

    prep_kernel<<<(N0 + 255) / 256, 256>>>(pos);
    warm_kernel<<<1, 32>>>();
    lin_in_kernel<<<N0 / 128, 128>>>(x, liW0, lib0, liW1, lib1);

    // level 0
    fps_kernel<N0, N1, 16, 4><<<1, FPS_T, sm0>>>((const float4*)p40, (int*)s0, (int*)sori);
    gather_kernel<<<N1 / 256, 256>>>((const float4*)p40, (const int*)s0, (float4*)p41, N1);
    sa_conv_kernel<N0><<<N1 * 32 / 256, 256>>>((const float4*)p40, (const float4*)p41,
                                               (const float4*)h0, (float4*)x1,
                                               saW0, sab0, saW1, sab1, N1);
    // level 1
    fps_kernel<N1, N2, 8, 3><<<1, FPS_T, sm1>>>((const float4*)p41, (int*)s1, (int*)sori);
    gather_kernel<<<N2 / 256, 256>>>((const float4*)p41, (const int*)s1, (float4*)p42, N2);
    sa_conv_kernel<N1><<<N2 * 32 / 256, 256>>>((const float4*)p41, (const float4*)p42,
                                               (const float4*)x1, (float4*)x2,
                                               saW0 + 361, sab0 + 19, saW1 + 304, sab1 + 16, N2);
    // level 2
    fps_kernel<N2, N3, 4, 3><<<1, FPS_T, sm2>>>((const float4*)p42, (int*)s2, (int*)sori);
    gather_kernel<<<N3 / 256, 256>>>((const float4*)p42, (const int*)s2, (float4*)p43, N3);
    sa_conv_kernel<N2><<<N3 * 32 / 256, 256>>>((const float4*)p42, (const float4*)p43,
                                               (const float4*)x2, (float4*)x3,
                                               saW0 + 722, sab0 + 38, saW1 + 608, sab1 + 32, N3);

    // FP path (coarse -> fine)
    fp_kernel<N3><<<N2 / 128, 128>>>((const float4*)p42, (const float4*)p43,
                                     (const float4*)x3, (const float4*)x2, (float4*)f2,
                                     fpW0 + 2 * 1024, fpb0 + 2 * 32, fpW1 + 2 * 512, fpb1 + 2 * 16,
                                     N2);
    fp_kernel<N2><<<N1 / 128, 128>>>((const float4*)p41, (const float4*)p42,
                                     (const float4*)f2, (const float4*)x1, (float4*)f1,
                                     fpW0 + 1024, fpb0 + 32, fpW1 + 512, fpb1 + 16, N1);
    fp_kernel<N1><<<N0 / 128, 128>>>((const float4*)p40, (const float4*)p41,
                                     (const float4*)f1, (const float4*)h0, (float4*)f0,
                                     fpW0, fpb0, fpW1, fpb1, N0);

    lin_out_kernel<<<N0 / 256, 256>>>(loW0, lob0, loW1, lob1, out);
}